// round 1
// baseline (speedup 1.0000x reference)
#include <cuda_runtime.h>

#define N_NODES 50000
#define N_EDGES 800000
#define D_IN    128
#define H1      128
#define H2      64

// ---------------- scratch (no allocations allowed) ----------------
__device__ int   g_deg[N_NODES];
__device__ int   g_cnt[N_NODES];
__device__ int   g_ptr[N_NODES + 1];
__device__ int   g_srcs[N_EDGES];
__device__ float g_y1[N_NODES * H1];   // reused as y2 (first N*H2)
__device__ float g_r1[N_NODES * H1];   // reused as r2 (first N*H2)
__device__ float g_h [N_NODES * H1];

// ---------------- f32x2 helpers (sm_103a packed fp32) ----------------
__device__ __forceinline__ unsigned long long pack2(float lo, float hi) {
    unsigned long long d;
    asm("mov.b64 %0, {%1, %2};" : "=l"(d)
        : "r"(__float_as_uint(lo)), "r"(__float_as_uint(hi)));
    return d;
}
__device__ __forceinline__ void unpack2(unsigned long long v, float& lo, float& hi) {
    unsigned int a, b;
    asm("mov.b64 {%0, %1}, %2;" : "=r"(a), "=r"(b) : "l"(v));
    lo = __uint_as_float(a); hi = __uint_as_float(b);
}
__device__ __forceinline__ void fma2(unsigned long long& d,
                                     unsigned long long a, unsigned long long b) {
    asm("fma.rn.f32x2 %0, %1, %2, %0;" : "+l"(d) : "l"(a), "l"(b));
}

// ---------------- CSR build ----------------
__global__ void k_zero() {
    int i = blockIdx.x * blockDim.x + threadIdx.x;
    if (i < N_NODES) { g_deg[i] = 0; g_cnt[i] = 0; }
}

__global__ void k_hist(const int* __restrict__ dst) {
    int e = blockIdx.x * blockDim.x + threadIdx.x;
    if (e < N_EDGES) atomicAdd(&g_deg[dst[e]], 1);
}

__global__ void k_scan() {
    __shared__ int s[1024];
    const int t = threadIdx.x;
    const int CH = (N_NODES + 1023) / 1024;   // 49
    const int base = t * CH;
    int sum = 0;
    for (int i = 0; i < CH; i++) {
        int idx = base + i;
        if (idx < N_NODES) sum += g_deg[idx];
    }
    s[t] = sum;
    __syncthreads();
    // inclusive Hillis-Steele scan over 1024
    for (int off = 1; off < 1024; off <<= 1) {
        int v = (t >= off) ? s[t - off] : 0;
        __syncthreads();
        s[t] += v;
        __syncthreads();
    }
    int run = s[t] - sum;   // exclusive base for this chunk
    for (int i = 0; i < CH; i++) {
        int idx = base + i;
        if (idx < N_NODES) { g_ptr[idx] = run; run += g_deg[idx]; }
    }
    if (t == 0) g_ptr[N_NODES] = N_EDGES;
}

__global__ void k_scatter(const int* __restrict__ src, const int* __restrict__ dst) {
    int e = blockIdx.x * blockDim.x + threadIdx.x;
    if (e < N_EDGES) {
        int d = dst[e];
        int pos = g_ptr[d] + atomicAdd(&g_cnt[d], 1);
        g_srcs[pos] = src[e];
    }
}

// ---------------- GEMM: C[N x M] = A[N x 128] @ W[128 x M] ----------------
// 256 threads, 64x64 tile, 4x4 per thread, packed f32x2 accumulators.
template <int M>
__global__ __launch_bounds__(256) void k_gemm(const float* __restrict__ A,
                                              const float* __restrict__ W,
                                              float* __restrict__ C) {
    __shared__ float As[16][68];   // [k][row], padded (272B rows, 16B aligned)
    __shared__ float Ws[16][64];   // [k][col]

    const int tid  = threadIdx.x;
    const int row0 = blockIdx.x * 64;
    const int col0 = blockIdx.y * 64;
    const int tx = tid & 15;        // col group (x4)
    const int ty = tid >> 4;        // row group (x4)

    const int lr = tid >> 2;        // 0..63 : A load row
    const int lq = tid & 3;         // 0..3  : A load k-quad
    const int wk = tid >> 4;        // 0..15 : W load k
    const int wc = tid & 15;        // 0..15 : W load col quad

    unsigned long long acc[4][2];
#pragma unroll
    for (int i = 0; i < 4; i++) { acc[i][0] = 0ull; acc[i][1] = 0ull; }

    for (int kb = 0; kb < 128; kb += 16) {
        float4 av = make_float4(0.f, 0.f, 0.f, 0.f);
        int gr = row0 + lr;
        if (gr < N_NODES)
            av = *(const float4*)&A[gr * 128 + kb + lq * 4];
        As[lq * 4 + 0][lr] = av.x;
        As[lq * 4 + 1][lr] = av.y;
        As[lq * 4 + 2][lr] = av.z;
        As[lq * 4 + 3][lr] = av.w;

        float4 wv = *(const float4*)&W[(kb + wk) * M + col0 + wc * 4];
        *(float4*)&Ws[wk][wc * 4] = wv;
        __syncthreads();

#pragma unroll
        for (int kk = 0; kk < 16; kk++) {
            float4 b = *(const float4*)&Ws[kk][tx * 4];
            unsigned long long b01 = pack2(b.x, b.y);
            unsigned long long b23 = pack2(b.z, b.w);
            float4 a = *(const float4*)&As[kk][ty * 4];
            unsigned long long aa;
            aa = pack2(a.x, a.x); fma2(acc[0][0], aa, b01); fma2(acc[0][1], aa, b23);
            aa = pack2(a.y, a.y); fma2(acc[1][0], aa, b01); fma2(acc[1][1], aa, b23);
            aa = pack2(a.z, a.z); fma2(acc[2][0], aa, b01); fma2(acc[2][1], aa, b23);
            aa = pack2(a.w, a.w); fma2(acc[3][0], aa, b01); fma2(acc[3][1], aa, b23);
        }
        __syncthreads();
    }

#pragma unroll
    for (int i = 0; i < 4; i++) {
        int gr = row0 + ty * 4 + i;
        if (gr < N_NODES) {
            float o0, o1, o2, o3;
            unpack2(acc[i][0], o0, o1);
            unpack2(acc[i][1], o2, o3);
            *(float4*)&C[gr * M + col0 + tx * 4] = make_float4(o0, o1, o2, o3);
        }
    }
}

// ---------------- gather-mean aggregation + epilogue ----------------
// out[n] = relu?( mean_{s in N(n)} y[s] + bias + r[n] )
template <int COLS, bool RELU>
__global__ __launch_bounds__(256) void k_agg(const float* __restrict__ y,
                                             const float* __restrict__ r,
                                             const float* __restrict__ bias,
                                             float* __restrict__ out) {
    int gw   = (blockIdx.x * blockDim.x + threadIdx.x) >> 5;   // node per warp
    int lane = threadIdx.x & 31;
    if (gw >= N_NODES) return;

    int p0 = g_ptr[gw];
    int p1 = g_ptr[gw + 1];
    float inv = 1.0f / (float)max(p1 - p0, 1);

    if (COLS == 128) {
        const int c = lane * 4;
        float4 acc = make_float4(0.f, 0.f, 0.f, 0.f);
        for (int j = p0; j < p1; j++) {
            int s = g_srcs[j];
            float4 v = __ldg((const float4*)&y[s * 128 + c]);
            acc.x += v.x; acc.y += v.y; acc.z += v.z; acc.w += v.w;
        }
        float4 rb = *(const float4*)&r[gw * 128 + c];
        float4 bb = __ldg((const float4*)&bias[c]);
        float4 o;
        o.x = fmaf(acc.x, inv, bb.x + rb.x);
        o.y = fmaf(acc.y, inv, bb.y + rb.y);
        o.z = fmaf(acc.z, inv, bb.z + rb.z);
        o.w = fmaf(acc.w, inv, bb.w + rb.w);
        if (RELU) {
            o.x = fmaxf(o.x, 0.f); o.y = fmaxf(o.y, 0.f);
            o.z = fmaxf(o.z, 0.f); o.w = fmaxf(o.w, 0.f);
        }
        *(float4*)&out[gw * 128 + c] = o;
    } else {   // COLS == 64
        const int c = lane * 2;
        float2 acc = make_float2(0.f, 0.f);
        for (int j = p0; j < p1; j++) {
            int s = g_srcs[j];
            float2 v = __ldg((const float2*)&y[s * 64 + c]);
            acc.x += v.x; acc.y += v.y;
        }
        float2 rb = *(const float2*)&r[gw * 64 + c];
        float2 bb = __ldg((const float2*)&bias[c]);
        float2 o;
        o.x = fmaf(acc.x, inv, bb.x + rb.x);
        o.y = fmaf(acc.y, inv, bb.y + rb.y);
        if (RELU) { o.x = fmaxf(o.x, 0.f); o.y = fmaxf(o.y, 0.f); }
        *(float2*)&out[gw * 64 + c] = o;
    }
}

// ---------------- launch ----------------
extern "C" void kernel_launch(void* const* d_in, const int* in_sizes, int n_in,
                              void* d_out, int out_size) {
    const float* x   = (const float*)d_in[0];
    const float* Wl1 = (const float*)d_in[1];
    const float* bl1 = (const float*)d_in[2];
    const float* Wr1 = (const float*)d_in[3];
    const float* Wl2 = (const float*)d_in[4];
    const float* bl2 = (const float*)d_in[5];
    const float* Wr2 = (const float*)d_in[6];
    const int*   ei  = (const int*)d_in[7];
    const int* src = ei;
    const int* dst = ei + N_EDGES;
    float* out = (float*)d_out;

    float *y1p, *r1p, *hp;
    cudaGetSymbolAddress((void**)&y1p, g_y1);
    cudaGetSymbolAddress((void**)&r1p, g_r1);
    cudaGetSymbolAddress((void**)&hp,  g_h);

    // CSR build
    k_zero   <<<(N_NODES + 255) / 256, 256>>>();
    k_hist   <<<(N_EDGES + 255) / 256, 256>>>(dst);
    k_scan   <<<1, 1024>>>();
    k_scatter<<<(N_EDGES + 255) / 256, 256>>>(src, dst);

    // layer 1: y1 = x@Wl1, r1 = x@Wr1, h = relu(mean-agg(y1) + bl1 + r1)
    dim3 g1((N_NODES + 63) / 64, H1 / 64);
    k_gemm<H1><<<g1, 256>>>(x, Wl1, y1p);
    k_gemm<H1><<<g1, 256>>>(x, Wr1, r1p);
    k_agg<128, true><<<(N_NODES + 7) / 8, 256>>>(y1p, r1p, bl1, hp);

    // layer 2: y2 = h@Wl2, r2 = h@Wr2, out = mean-agg(y2) + bl2 + r2
    dim3 g2((N_NODES + 63) / 64, H2 / 64);
    k_gemm<H2><<<g2, 256>>>(hp, Wl2, y1p);   // y2 reuses y1 buffer
    k_gemm<H2><<<g2, 256>>>(hp, Wr2, r1p);   // r2 reuses r1 buffer
    k_agg<64, false><<<(N_NODES + 7) / 8, 256>>>(y1p, r1p, bl2, out);
}

// round 3
// speedup vs baseline: 1.2380x; 1.2380x over previous
#include <cuda_runtime.h>
#include <cstdint>

#define N_NODES 50000
#define N_EDGES 800000
#define H1      128
#define H2      64

// ---------------- scratch (no allocations allowed) ----------------
__device__ int   g_deg[N_NODES];
__device__ int   g_cnt[N_NODES];
__device__ int   g_ptr[N_NODES + 1];
__device__ int   g_srcs[N_EDGES];
__device__ float g_y1[N_NODES * H1];   // reused as y2 (first N*H2)
__device__ float g_r1[N_NODES * H1];   // reused as r2 (first N*H2)
__device__ float g_h [N_NODES * H1];

// ---------------- tf32 helpers ----------------
__device__ __forceinline__ float f2tf32(float f) {
    uint32_t u;
    asm("cvt.rna.tf32.f32 %0, %1;" : "=r"(u) : "f"(f));
    return __uint_as_float(u);
}
__device__ __forceinline__ void mma_tf32(float* c, const float* a, const float* b) {
    asm volatile(
        "mma.sync.aligned.m16n8k8.row.col.f32.tf32.tf32.f32 "
        "{%0,%1,%2,%3}, {%4,%5,%6,%7}, {%8,%9}, {%0,%1,%2,%3};"
        : "+f"(c[0]), "+f"(c[1]), "+f"(c[2]), "+f"(c[3])
        : "r"(__float_as_uint(a[0])), "r"(__float_as_uint(a[1])),
          "r"(__float_as_uint(a[2])), "r"(__float_as_uint(a[3])),
          "r"(__float_as_uint(b[0])), "r"(__float_as_uint(b[1])));
}

// ---------------- CSR build ----------------
__global__ void k_zero() {
    int i = blockIdx.x * blockDim.x + threadIdx.x;
    if (i < N_NODES) { g_deg[i] = 0; g_cnt[i] = 0; }
}
__global__ void k_hist(const int* __restrict__ dst) {
    int e = blockIdx.x * blockDim.x + threadIdx.x;
    if (e < N_EDGES) atomicAdd(&g_deg[dst[e]], 1);
}
__global__ void k_scan() {
    __shared__ int s[1024];
    const int t = threadIdx.x;
    const int CH = (N_NODES + 1023) / 1024;
    const int base = t * CH;
    int sum = 0;
    for (int i = 0; i < CH; i++) {
        int idx = base + i;
        if (idx < N_NODES) sum += g_deg[idx];
    }
    s[t] = sum;
    __syncthreads();
    for (int off = 1; off < 1024; off <<= 1) {
        int v = (t >= off) ? s[t - off] : 0;
        __syncthreads();
        s[t] += v;
        __syncthreads();
    }
    int run = s[t] - sum;
    for (int i = 0; i < CH; i++) {
        int idx = base + i;
        if (idx < N_NODES) { g_ptr[idx] = run; run += g_deg[idx]; }
    }
    if (t == 0) g_ptr[N_NODES] = N_EDGES;
}
__global__ void k_scatter(const int* __restrict__ src, const int* __restrict__ dst) {
    int e = blockIdx.x * blockDim.x + threadIdx.x;
    if (e < N_EDGES) {
        int d = dst[e];
        int pos = g_ptr[d] + atomicAdd(&g_cnt[d], 1);
        g_srcs[pos] = src[e];
    }
}

// ---------------- tensor-core tf32 GEMM (mma.sync, sm_80-path) ----------------
// Block: 256 thr, tile 128 rows x 64 cols, K=128 one-shot in smem.
// Col blocks [0, M_OUT/64) -> Y via Wl ; rest -> R via Wr.
// A ld = 132 floats, W ld = 76 floats: conflict-free fragment LDS.
template <int M_OUT>
__global__ __launch_bounds__(256) void k_mma(const float* __restrict__ A,
                                             const float* __restrict__ Wl,
                                             const float* __restrict__ Wr,
                                             float* __restrict__ Y,
                                             float* __restrict__ R) {
    extern __shared__ float sm[];
    float* As = sm;                     // [128][132]
    float* Ws = sm + 128 * 132;         // [128][76]

    const int tid  = threadIdx.x;
    const int row0 = blockIdx.x * 128;
    const int col0 = blockIdx.y * 64;

    const float* W;
    float* D;
    int cw;
    if (col0 < M_OUT) { W = Wl; D = Y; cw = col0; }
    else              { W = Wr; D = R; cw = col0 - M_OUT; }

    // --- stage A (128 x 128), tf32-rounded ---
    for (int idx = tid; idx < 128 * 32; idx += 256) {
        int r = idx >> 5, q = (idx & 31) << 2;
        float4 v = make_float4(0.f, 0.f, 0.f, 0.f);
        int gr = row0 + r;
        if (gr < N_NODES) v = *(const float4*)&A[(size_t)gr * 128 + q];
        float* p = &As[r * 132 + q];
        p[0] = f2tf32(v.x); p[1] = f2tf32(v.y);
        p[2] = f2tf32(v.z); p[3] = f2tf32(v.w);
    }
    // --- stage W (128 k x 64 n), tf32-rounded ---
    for (int idx = tid; idx < 128 * 16; idx += 256) {
        int k = idx >> 4, q = (idx & 15) << 2;
        float4 v = *(const float4*)&W[(size_t)k * M_OUT + cw + q];
        float* p = &Ws[k * 76 + q];
        p[0] = f2tf32(v.x); p[1] = f2tf32(v.y);
        p[2] = f2tf32(v.z); p[3] = f2tf32(v.w);
    }
    __syncthreads();

    const int wid  = tid >> 5;
    const int lane = tid & 31;
    const int gid  = lane >> 2;
    const int tig  = lane & 3;
    const int wr0  = (wid & 3) * 32;    // warp rows in tile
    const int wc0  = (wid >> 2) * 32;   // warp cols in tile

    float acc[2][4][4];
#pragma unroll
    for (int mt = 0; mt < 2; mt++)
#pragma unroll
        for (int nt = 0; nt < 4; nt++)
#pragma unroll
            for (int i = 0; i < 4; i++) acc[mt][nt][i] = 0.f;

#pragma unroll
    for (int ks = 0; ks < 16; ks++) {
        const int k0 = ks * 8;
        float a[2][4], b[4][2];
#pragma unroll
        for (int mt = 0; mt < 2; mt++) {
            int r = wr0 + mt * 16 + gid;
            a[mt][0] = As[r * 132 + k0 + tig];
            a[mt][1] = As[(r + 8) * 132 + k0 + tig];
            a[mt][2] = As[r * 132 + k0 + tig + 4];
            a[mt][3] = As[(r + 8) * 132 + k0 + tig + 4];
        }
#pragma unroll
        for (int nt = 0; nt < 4; nt++) {
            int c = wc0 + nt * 8 + gid;
            b[nt][0] = Ws[(k0 + tig) * 76 + c];
            b[nt][1] = Ws[(k0 + tig + 4) * 76 + c];
        }
#pragma unroll
        for (int mt = 0; mt < 2; mt++)
#pragma unroll
            for (int nt = 0; nt < 4; nt++)
                mma_tf32(acc[mt][nt], a[mt], b[nt]);
    }

    // --- store C ---
#pragma unroll
    for (int mt = 0; mt < 2; mt++) {
        int r = row0 + wr0 + mt * 16 + gid;
#pragma unroll
        for (int nt = 0; nt < 4; nt++) {
            int c = cw + wc0 + nt * 8 + 2 * tig;
            if (r < N_NODES)
                *(float2*)&D[(size_t)r * M_OUT + c] =
                    make_float2(acc[mt][nt][0], acc[mt][nt][1]);
            if (r + 8 < N_NODES)
                *(float2*)&D[(size_t)(r + 8) * M_OUT + c] =
                    make_float2(acc[mt][nt][2], acc[mt][nt][3]);
        }
    }
}

// ---------------- gather-mean aggregation + epilogue ----------------
template <int COLS, bool RELU>
__global__ __launch_bounds__(256) void k_agg(const float* __restrict__ y,
                                             const float* __restrict__ r,
                                             const float* __restrict__ bias,
                                             float* __restrict__ out) {
    int gw   = (blockIdx.x * blockDim.x + threadIdx.x) >> 5;
    int lane = threadIdx.x & 31;
    if (gw >= N_NODES) return;

    int p0 = g_ptr[gw];
    int p1 = g_ptr[gw + 1];
    float inv = 1.0f / (float)max(p1 - p0, 1);

    if (COLS == 128) {
        const int c = lane * 4;
        float4 acc = make_float4(0.f, 0.f, 0.f, 0.f);
        for (int j = p0; j < p1; j++) {
            int s = g_srcs[j];
            float4 v = __ldg((const float4*)&y[(size_t)s * 128 + c]);
            acc.x += v.x; acc.y += v.y; acc.z += v.z; acc.w += v.w;
        }
        float4 rb = *(const float4*)&r[(size_t)gw * 128 + c];
        float4 bb = __ldg((const float4*)&bias[c]);
        float4 o;
        o.x = fmaf(acc.x, inv, bb.x + rb.x);
        o.y = fmaf(acc.y, inv, bb.y + rb.y);
        o.z = fmaf(acc.z, inv, bb.z + rb.z);
        o.w = fmaf(acc.w, inv, bb.w + rb.w);
        if (RELU) {
            o.x = fmaxf(o.x, 0.f); o.y = fmaxf(o.y, 0.f);
            o.z = fmaxf(o.z, 0.f); o.w = fmaxf(o.w, 0.f);
        }
        *(float4*)&out[(size_t)gw * 128 + c] = o;
    } else {
        const int c = lane * 2;
        float2 acc = make_float2(0.f, 0.f);
        for (int j = p0; j < p1; j++) {
            int s = g_srcs[j];
            float2 v = __ldg((const float2*)&y[(size_t)s * 64 + c]);
            acc.x += v.x; acc.y += v.y;
        }
        float2 rb = *(const float2*)&r[(size_t)gw * 64 + c];
        float2 bb = __ldg((const float2*)&bias[c]);
        float2 o;
        o.x = fmaf(acc.x, inv, bb.x + rb.x);
        o.y = fmaf(acc.y, inv, bb.y + rb.y);
        if (RELU) { o.x = fmaxf(o.x, 0.f); o.y = fmaxf(o.y, 0.f); }
        *(float2*)&out[(size_t)gw * 64 + c] = o;
    }
}

// ---------------- launch ----------------
extern "C" void kernel_launch(void* const* d_in, const int* in_sizes, int n_in,
                              void* d_out, int out_size) {
    const float* x   = (const float*)d_in[0];
    const float* Wl1 = (const float*)d_in[1];
    const float* bl1 = (const float*)d_in[2];
    const float* Wr1 = (const float*)d_in[3];
    const float* Wl2 = (const float*)d_in[4];
    const float* bl2 = (const float*)d_in[5];
    const float* Wr2 = (const float*)d_in[6];
    const int*   ei  = (const int*)d_in[7];
    const int* src = ei;
    const int* dst = ei + N_EDGES;
    float* out = (float*)d_out;

    float *y1p, *r1p, *hp;
    cudaGetSymbolAddress((void**)&y1p, g_y1);
    cudaGetSymbolAddress((void**)&r1p, g_r1);
    cudaGetSymbolAddress((void**)&hp,  g_h);

    constexpr int SMEM = (128 * 132 + 128 * 76) * 4;   // 106496 B
    cudaFuncSetAttribute(k_mma<128>,
                         cudaFuncAttributeMaxDynamicSharedMemorySize, SMEM);
    cudaFuncSetAttribute(k_mma<64>,
                         cudaFuncAttributeMaxDynamicSharedMemorySize, SMEM);

    // CSR build
    k_zero   <<<(N_NODES + 255) / 256, 256>>>();
    k_hist   <<<(N_EDGES + 255) / 256, 256>>>(dst);
    k_scan   <<<1, 1024>>>();
    k_scatter<<<(N_EDGES + 255) / 256, 256>>>(src, dst);

    const int n_tiles = (N_NODES + 127) / 128;   // 391

    // layer 1: [y1 | r1] = x @ [Wl1 | Wr1], h = relu(mean-agg(y1) + bl1 + r1)
    k_mma<128><<<dim3(n_tiles, 4), 256, SMEM>>>(x, Wl1, Wr1, y1p, r1p);
    k_agg<128, true><<<(N_NODES + 7) / 8, 256>>>(y1p, r1p, bl1, hp);

    // layer 2: [y2 | r2] = h @ [Wl2 | Wr2], out = mean-agg(y2) + bl2 + r2
    k_mma<64><<<dim3(n_tiles, 2), 256, SMEM>>>(hp, Wl2, Wr2, y1p, r1p);
    k_agg<64, false><<<(N_NODES + 7) / 8, 256>>>(y1p, r1p, bl2, out);
}

// round 4
// speedup vs baseline: 1.4422x; 1.1649x over previous
#include <cuda_runtime.h>
#include <cstdint>

#define N_NODES 50000
#define N_EDGES 800000
#define H1      128
#define H2      64

// ---------------- scratch (no allocations allowed) ----------------
__device__ int   g_deg[N_NODES];
__device__ int   g_ptr[N_NODES + 1];
__device__ int   g_rank[N_EDGES];
__device__ int   g_srcs[N_EDGES];
__device__ int   g_bsum[64];
__device__ int   g_boff[64];
__device__ float g_y1[N_NODES * H1];   // reused as y2 (first N*H2)
__device__ float g_r1[N_NODES * H1];   // reused as r2 (first N*H2)
__device__ float g_h [N_NODES * H1];

// ---------------- tf32 helpers ----------------
__device__ __forceinline__ float f2tf32(float f) {
    uint32_t u;
    asm("cvt.rna.tf32.f32 %0, %1;" : "=r"(u) : "f"(f));
    return __uint_as_float(u);
}
__device__ __forceinline__ void mma_tf32(float* c, const float* a, const float* b) {
    asm volatile(
        "mma.sync.aligned.m16n8k8.row.col.f32.tf32.tf32.f32 "
        "{%0,%1,%2,%3}, {%4,%5,%6,%7}, {%8,%9}, {%0,%1,%2,%3};"
        : "+f"(c[0]), "+f"(c[1]), "+f"(c[2]), "+f"(c[3])
        : "r"(__float_as_uint(a[0])), "r"(__float_as_uint(a[1])),
          "r"(__float_as_uint(a[2])), "r"(__float_as_uint(a[3])),
          "r"(__float_as_uint(b[0])), "r"(__float_as_uint(b[1])));
}

// ---------------- CSR build ----------------
__global__ void k_zero() {
    int i = blockIdx.x * blockDim.x + threadIdx.x;
    if (i < N_NODES) g_deg[i] = 0;
}
// histogram; also records each edge's rank within its dst bucket
__global__ void k_hist(const int* __restrict__ dst) {
    int e = blockIdx.x * blockDim.x + threadIdx.x;
    if (e < N_EDGES) g_rank[e] = atomicAdd(&g_deg[dst[e]], 1);
}
// phase A: per-block (1024-wide) exclusive scan of degrees
#define SCAN_BLOCKS 49
__global__ __launch_bounds__(1024) void k_scan_a() {
    __shared__ int s[1024];
    int t = threadIdx.x;
    int i = blockIdx.x * 1024 + t;
    int val = (i < N_NODES) ? g_deg[i] : 0;
    s[t] = val;
    __syncthreads();
#pragma unroll
    for (int off = 1; off < 1024; off <<= 1) {
        int v = (t >= off) ? s[t - off] : 0;
        __syncthreads();
        s[t] += v;
        __syncthreads();
    }
    if (i < N_NODES) g_ptr[i] = s[t] - val;          // exclusive within block
    if (t == 1023) g_bsum[blockIdx.x] = s[t];        // block total
}
// phase B: exclusive scan of the 49 block sums
__global__ void k_scan_b() {
    __shared__ int s[64];
    int t = threadIdx.x;
    int val = (t < SCAN_BLOCKS) ? g_bsum[t] : 0;
    s[t] = val;
    __syncthreads();
#pragma unroll
    for (int off = 1; off < 64; off <<= 1) {
        int v = (t >= off) ? s[t - off] : 0;
        __syncthreads();
        s[t] += v;
        __syncthreads();
    }
    if (t < SCAN_BLOCKS) g_boff[t] = s[t] - val;
}
// phase C: add block offsets
__global__ __launch_bounds__(1024) void k_scan_c() {
    int i = blockIdx.x * 1024 + threadIdx.x;
    if (i < N_NODES) g_ptr[i] += g_boff[blockIdx.x];
    if (i == 0) g_ptr[N_NODES] = N_EDGES;
}
// atomic-free scatter using precomputed ranks
__global__ void k_scatter(const int* __restrict__ src, const int* __restrict__ dst) {
    int e = blockIdx.x * blockDim.x + threadIdx.x;
    if (e < N_EDGES)
        g_srcs[g_ptr[dst[e]] + g_rank[e]] = src[e];
}

// ---------------- tensor-core tf32 GEMM (mma.sync) ----------------
// One CTA: A tile 128 rows (staged once) x one 64-col block of BOTH Wl and Wr.
// grid = (row_tiles, M_OUT/64).
template <int M_OUT>
__global__ __launch_bounds__(256) void k_mma(const float* __restrict__ A,
                                             const float* __restrict__ Wl,
                                             const float* __restrict__ Wr,
                                             float* __restrict__ Y,
                                             float* __restrict__ R) {
    extern __shared__ float sm[];
    float* As  = sm;                         // [128][132]
    float* Wsl = sm + 128 * 132;             // [128][76]
    float* Wsr = Wsl + 128 * 76;             // [128][76]

    const int tid  = threadIdx.x;
    const int row0 = blockIdx.x * 128;
    const int cw   = blockIdx.y * 64;

    // --- stage A (128 x 128), tf32-rounded ---
    for (int idx = tid; idx < 128 * 32; idx += 256) {
        int r = idx >> 5, q = (idx & 31) << 2;
        float4 v = make_float4(0.f, 0.f, 0.f, 0.f);
        int gr = row0 + r;
        if (gr < N_NODES) v = *(const float4*)&A[(size_t)gr * 128 + q];
        float* p = &As[r * 132 + q];
        p[0] = f2tf32(v.x); p[1] = f2tf32(v.y);
        p[2] = f2tf32(v.z); p[3] = f2tf32(v.w);
    }
    // --- stage Wl, Wr (128 k x 64 n each), tf32-rounded ---
    for (int idx = tid; idx < 128 * 16; idx += 256) {
        int k = idx >> 4, q = (idx & 15) << 2;
        float4 vl = *(const float4*)&Wl[(size_t)k * M_OUT + cw + q];
        float4 vr = *(const float4*)&Wr[(size_t)k * M_OUT + cw + q];
        float* pl = &Wsl[k * 76 + q];
        float* pr = &Wsr[k * 76 + q];
        pl[0] = f2tf32(vl.x); pl[1] = f2tf32(vl.y);
        pl[2] = f2tf32(vl.z); pl[3] = f2tf32(vl.w);
        pr[0] = f2tf32(vr.x); pr[1] = f2tf32(vr.y);
        pr[2] = f2tf32(vr.z); pr[3] = f2tf32(vr.w);
    }
    __syncthreads();

    const int wid  = tid >> 5;
    const int lane = tid & 31;
    const int gid  = lane >> 2;
    const int tig  = lane & 3;
    const int wr0  = (wid & 3) * 32;    // warp rows in tile
    const int wc0  = (wid >> 2) * 32;   // warp cols in tile (0 or 32)

    float accl[2][4][4], accr[2][4][4];
#pragma unroll
    for (int mt = 0; mt < 2; mt++)
#pragma unroll
        for (int nt = 0; nt < 4; nt++)
#pragma unroll
            for (int i = 0; i < 4; i++) { accl[mt][nt][i] = 0.f; accr[mt][nt][i] = 0.f; }

#pragma unroll
    for (int ks = 0; ks < 16; ks++) {
        const int k0 = ks * 8;
        float a[2][4], bl[4][2], br[4][2];
#pragma unroll
        for (int mt = 0; mt < 2; mt++) {
            int r = wr0 + mt * 16 + gid;
            a[mt][0] = As[r * 132 + k0 + tig];
            a[mt][1] = As[(r + 8) * 132 + k0 + tig];
            a[mt][2] = As[r * 132 + k0 + tig + 4];
            a[mt][3] = As[(r + 8) * 132 + k0 + tig + 4];
        }
#pragma unroll
        for (int nt = 0; nt < 4; nt++) {
            int c = wc0 + nt * 8 + gid;
            bl[nt][0] = Wsl[(k0 + tig) * 76 + c];
            bl[nt][1] = Wsl[(k0 + tig + 4) * 76 + c];
            br[nt][0] = Wsr[(k0 + tig) * 76 + c];
            br[nt][1] = Wsr[(k0 + tig + 4) * 76 + c];
        }
#pragma unroll
        for (int mt = 0; mt < 2; mt++)
#pragma unroll
            for (int nt = 0; nt < 4; nt++) {
                mma_tf32(accl[mt][nt], a[mt], bl[nt]);
                mma_tf32(accr[mt][nt], a[mt], br[nt]);
            }
    }

    // --- store ---
#pragma unroll
    for (int mt = 0; mt < 2; mt++) {
        int r = row0 + wr0 + mt * 16 + gid;
#pragma unroll
        for (int nt = 0; nt < 4; nt++) {
            int c = cw + wc0 + nt * 8 + 2 * tig;
            if (r < N_NODES) {
                *(float2*)&Y[(size_t)r * M_OUT + c] =
                    make_float2(accl[mt][nt][0], accl[mt][nt][1]);
                *(float2*)&R[(size_t)r * M_OUT + c] =
                    make_float2(accr[mt][nt][0], accr[mt][nt][1]);
            }
            if (r + 8 < N_NODES) {
                *(float2*)&Y[(size_t)(r + 8) * M_OUT + c] =
                    make_float2(accl[mt][nt][2], accl[mt][nt][3]);
                *(float2*)&R[(size_t)(r + 8) * M_OUT + c] =
                    make_float2(accr[mt][nt][2], accr[mt][nt][3]);
            }
        }
    }
}

// ---------------- gather-mean aggregation + epilogue (MLP-4 unrolled) ----------------
template <int COLS, bool RELU>
__global__ __launch_bounds__(256) void k_agg(const float* __restrict__ y,
                                             const float* __restrict__ r,
                                             const float* __restrict__ bias,
                                             float* __restrict__ out) {
    int gw   = (blockIdx.x * blockDim.x + threadIdx.x) >> 5;
    int lane = threadIdx.x & 31;
    if (gw >= N_NODES) return;

    int p0 = g_ptr[gw];
    int p1 = g_ptr[gw + 1];
    float inv = 1.0f / (float)max(p1 - p0, 1);

    if (COLS == 128) {
        const int c = lane * 4;
        float4 a0 = make_float4(0.f, 0.f, 0.f, 0.f);
        float4 a1 = make_float4(0.f, 0.f, 0.f, 0.f);
        int j = p0;
        for (; j + 4 <= p1; j += 4) {
            int s0 = __ldg(&g_srcs[j]),     s1 = __ldg(&g_srcs[j + 1]);
            int s2 = __ldg(&g_srcs[j + 2]), s3 = __ldg(&g_srcs[j + 3]);
            float4 v0 = __ldg((const float4*)&y[(size_t)s0 * 128 + c]);
            float4 v1 = __ldg((const float4*)&y[(size_t)s1 * 128 + c]);
            float4 v2 = __ldg((const float4*)&y[(size_t)s2 * 128 + c]);
            float4 v3 = __ldg((const float4*)&y[(size_t)s3 * 128 + c]);
            a0.x += v0.x; a0.y += v0.y; a0.z += v0.z; a0.w += v0.w;
            a1.x += v1.x; a1.y += v1.y; a1.z += v1.z; a1.w += v1.w;
            a0.x += v2.x; a0.y += v2.y; a0.z += v2.z; a0.w += v2.w;
            a1.x += v3.x; a1.y += v3.y; a1.z += v3.z; a1.w += v3.w;
        }
        for (; j < p1; j++) {
            int s = __ldg(&g_srcs[j]);
            float4 v = __ldg((const float4*)&y[(size_t)s * 128 + c]);
            a0.x += v.x; a0.y += v.y; a0.z += v.z; a0.w += v.w;
        }
        float4 rb = *(const float4*)&r[(size_t)gw * 128 + c];
        float4 bb = __ldg((const float4*)&bias[c]);
        float4 o;
        o.x = fmaf(a0.x + a1.x, inv, bb.x + rb.x);
        o.y = fmaf(a0.y + a1.y, inv, bb.y + rb.y);
        o.z = fmaf(a0.z + a1.z, inv, bb.z + rb.z);
        o.w = fmaf(a0.w + a1.w, inv, bb.w + rb.w);
        if (RELU) {
            o.x = fmaxf(o.x, 0.f); o.y = fmaxf(o.y, 0.f);
            o.z = fmaxf(o.z, 0.f); o.w = fmaxf(o.w, 0.f);
        }
        *(float4*)&out[(size_t)gw * 128 + c] = o;
    } else {
        const int c = lane * 2;
        float2 a0 = make_float2(0.f, 0.f);
        float2 a1 = make_float2(0.f, 0.f);
        int j = p0;
        for (; j + 4 <= p1; j += 4) {
            int s0 = __ldg(&g_srcs[j]),     s1 = __ldg(&g_srcs[j + 1]);
            int s2 = __ldg(&g_srcs[j + 2]), s3 = __ldg(&g_srcs[j + 3]);
            float2 v0 = __ldg((const float2*)&y[(size_t)s0 * 64 + c]);
            float2 v1 = __ldg((const float2*)&y[(size_t)s1 * 64 + c]);
            float2 v2 = __ldg((const float2*)&y[(size_t)s2 * 64 + c]);
            float2 v3 = __ldg((const float2*)&y[(size_t)s3 * 64 + c]);
            a0.x += v0.x; a0.y += v0.y;
            a1.x += v1.x; a1.y += v1.y;
            a0.x += v2.x; a0.y += v2.y;
            a1.x += v3.x; a1.y += v3.y;
        }
        for (; j < p1; j++) {
            int s = __ldg(&g_srcs[j]);
            float2 v = __ldg((const float2*)&y[(size_t)s * 64 + c]);
            a0.x += v.x; a0.y += v.y;
        }
        float2 rb = *(const float2*)&r[(size_t)gw * 64 + c];
        float2 bb = __ldg((const float2*)&bias[c]);
        float2 o;
        o.x = fmaf(a0.x + a1.x, inv, bb.x + rb.x);
        o.y = fmaf(a0.y + a1.y, inv, bb.y + rb.y);
        if (RELU) { o.x = fmaxf(o.x, 0.f); o.y = fmaxf(o.y, 0.f); }
        *(float2*)&out[(size_t)gw * 64 + c] = o;
    }
}

// ---------------- launch ----------------
extern "C" void kernel_launch(void* const* d_in, const int* in_sizes, int n_in,
                              void* d_out, int out_size) {
    const float* x   = (const float*)d_in[0];
    const float* Wl1 = (const float*)d_in[1];
    const float* bl1 = (const float*)d_in[2];
    const float* Wr1 = (const float*)d_in[3];
    const float* Wl2 = (const float*)d_in[4];
    const float* bl2 = (const float*)d_in[5];
    const float* Wr2 = (const float*)d_in[6];
    const int*   ei  = (const int*)d_in[7];
    const int* src = ei;
    const int* dst = ei + N_EDGES;
    float* out = (float*)d_out;

    float *y1p, *r1p, *hp;
    cudaGetSymbolAddress((void**)&y1p, g_y1);
    cudaGetSymbolAddress((void**)&r1p, g_r1);
    cudaGetSymbolAddress((void**)&hp,  g_h);

    constexpr int SMEM = (128 * 132 + 2 * 128 * 76) * 4;   // 145408 B
    cudaFuncSetAttribute(k_mma<128>,
                         cudaFuncAttributeMaxDynamicSharedMemorySize, SMEM);
    cudaFuncSetAttribute(k_mma<64>,
                         cudaFuncAttributeMaxDynamicSharedMemorySize, SMEM);

    // CSR build
    k_zero   <<<(N_NODES + 255) / 256, 256>>>();
    k_hist   <<<(N_EDGES + 255) / 256, 256>>>(dst);
    k_scan_a <<<SCAN_BLOCKS, 1024>>>();
    k_scan_b <<<1, 64>>>();
    k_scan_c <<<SCAN_BLOCKS, 1024>>>();
    k_scatter<<<(N_EDGES + 255) / 256, 256>>>(src, dst);

    const int n_tiles = (N_NODES + 127) / 128;   // 391

    // layer 1: [y1 | r1] = x @ [Wl1 | Wr1], h = relu(mean-agg(y1) + bl1 + r1)
    k_mma<128><<<dim3(n_tiles, 2), 256, SMEM>>>(x, Wl1, Wr1, y1p, r1p);
    k_agg<128, true><<<(N_NODES + 7) / 8, 256>>>(y1p, r1p, bl1, hp);

    // layer 2: [y2 | r2] = h @ [Wl2 | Wr2], out = mean-agg(y2) + bl2 + r2
    k_mma<64><<<dim3(n_tiles, 1), 256, SMEM>>>(hp, Wl2, Wr2, y1p, r1p);
    k_agg<64, false><<<(N_NODES + 7) / 8, 256>>>(y1p, r1p, bl2, out);
}

// round 5
// speedup vs baseline: 1.4978x; 1.0386x over previous
#include <cuda_runtime.h>
#include <cuda_fp16.h>
#include <cstdint>

#define N_NODES 50000
#define N_EDGES 800000
#define H1      128
#define H2      64

// ---------------- scratch (no allocations allowed) ----------------
__device__ int    g_deg[N_NODES];
__device__ int    g_ptr[N_NODES + 1];
__device__ int    g_rank[N_EDGES];
__device__ int    g_srcs[N_EDGES];
__device__ int    g_bsum[64];
__device__ __half g_yh[N_NODES * H1];   // fp16 lin_l output (reused by layer 2)
__device__ float  g_r1[N_NODES * H1];   // fp32 lin_r output (reused by layer 2)
__device__ float  g_h [N_NODES * H1];

// ---------------- tf32 helpers ----------------
__device__ __forceinline__ float f2tf32(float f) {
    uint32_t u;
    asm("cvt.rna.tf32.f32 %0, %1;" : "=r"(u) : "f"(f));
    return __uint_as_float(u);
}
__device__ __forceinline__ void mma_tf32(float* c, const float* a, const float* b) {
    asm volatile(
        "mma.sync.aligned.m16n8k8.row.col.f32.tf32.tf32.f32 "
        "{%0,%1,%2,%3}, {%4,%5,%6,%7}, {%8,%9}, {%0,%1,%2,%3};"
        : "+f"(c[0]), "+f"(c[1]), "+f"(c[2]), "+f"(c[3])
        : "r"(__float_as_uint(a[0])), "r"(__float_as_uint(a[1])),
          "r"(__float_as_uint(a[2])), "r"(__float_as_uint(a[3])),
          "r"(__float_as_uint(b[0])), "r"(__float_as_uint(b[1])));
}

// ---------------- CSR build ----------------
__global__ void k_zero() {
    int i = blockIdx.x * blockDim.x + threadIdx.x;
    if (i < N_NODES) g_deg[i] = 0;
}
__global__ void k_hist(const int* __restrict__ dst) {
    int e = blockIdx.x * blockDim.x + threadIdx.x;
    if (e < N_EDGES) g_rank[e] = atomicAdd(&g_deg[dst[e]], 1);
}
#define SCAN_BLOCKS 49
__global__ __launch_bounds__(1024) void k_scan_a() {
    __shared__ int s[1024];
    int t = threadIdx.x;
    int i = blockIdx.x * 1024 + t;
    int val = (i < N_NODES) ? g_deg[i] : 0;
    s[t] = val;
    __syncthreads();
#pragma unroll
    for (int off = 1; off < 1024; off <<= 1) {
        int v = (t >= off) ? s[t - off] : 0;
        __syncthreads();
        s[t] += v;
        __syncthreads();
    }
    if (i < N_NODES) g_ptr[i] = s[t] - val;          // exclusive within block
    if (t == 1023) g_bsum[blockIdx.x] = s[t];        // block total
}
// phase C: each block redundantly scans the 49 block sums (cheap), adds offset
__global__ __launch_bounds__(1024) void k_scan_c() {
    __shared__ int s[64];
    int t = threadIdx.x;
    if (t < 64) s[t] = (t < SCAN_BLOCKS) ? g_bsum[t] : 0;
    __syncthreads();
    if (t < 64) {
#pragma unroll
        for (int off = 1; off < 64; off <<= 1) {
            int v = (t >= off) ? s[t - off] : 0;
            __syncwarp();  // not sufficient across 64 threads; use full sync below
            s[t] += v;
            __syncwarp();
        }
    }
    __syncthreads();
    // s[] above may race across the two warps; recompute safely: serial in t==0
    __shared__ int off_s;
    if (t == 0) {
        int acc = 0;
        for (int b = 0; b < blockIdx.x; b++) acc += g_bsum[b];
        off_s = acc;
    }
    __syncthreads();
    int i = blockIdx.x * 1024 + t;
    if (i < N_NODES) g_ptr[i] += off_s;
    if (i == 0) g_ptr[N_NODES] = N_EDGES;
}
__global__ void k_scatter(const int* __restrict__ src, const int* __restrict__ dst) {
    int e = blockIdx.x * blockDim.x + threadIdx.x;
    if (e < N_EDGES)
        g_srcs[g_ptr[dst[e]] + g_rank[e]] = src[e];
}

// ---------------- tensor-core tf32 GEMM (mma.sync) ----------------
// One CTA: A tile 128 rows x one 64-col block of BOTH Wl (-> fp16 Y) and Wr (-> fp32 R).
template <int M_OUT>
__global__ __launch_bounds__(256) void k_mma(const float* __restrict__ A,
                                             const float* __restrict__ Wl,
                                             const float* __restrict__ Wr,
                                             __half* __restrict__ Y,
                                             float* __restrict__ R) {
    extern __shared__ float sm[];
    float* As  = sm;                         // [128][132]
    float* Wsl = sm + 128 * 132;             // [128][76]
    float* Wsr = Wsl + 128 * 76;             // [128][76]

    const int tid  = threadIdx.x;
    const int row0 = blockIdx.x * 128;
    const int cw   = blockIdx.y * 64;

    for (int idx = tid; idx < 128 * 32; idx += 256) {
        int r = idx >> 5, q = (idx & 31) << 2;
        float4 v = make_float4(0.f, 0.f, 0.f, 0.f);
        int gr = row0 + r;
        if (gr < N_NODES) v = *(const float4*)&A[(size_t)gr * 128 + q];
        float* p = &As[r * 132 + q];
        p[0] = f2tf32(v.x); p[1] = f2tf32(v.y);
        p[2] = f2tf32(v.z); p[3] = f2tf32(v.w);
    }
    for (int idx = tid; idx < 128 * 16; idx += 256) {
        int k = idx >> 4, q = (idx & 15) << 2;
        float4 vl = *(const float4*)&Wl[(size_t)k * M_OUT + cw + q];
        float4 vr = *(const float4*)&Wr[(size_t)k * M_OUT + cw + q];
        float* pl = &Wsl[k * 76 + q];
        float* pr = &Wsr[k * 76 + q];
        pl[0] = f2tf32(vl.x); pl[1] = f2tf32(vl.y);
        pl[2] = f2tf32(vl.z); pl[3] = f2tf32(vl.w);
        pr[0] = f2tf32(vr.x); pr[1] = f2tf32(vr.y);
        pr[2] = f2tf32(vr.z); pr[3] = f2tf32(vr.w);
    }
    __syncthreads();

    const int wid  = tid >> 5;
    const int lane = tid & 31;
    const int gid  = lane >> 2;
    const int tig  = lane & 3;
    const int wr0  = (wid & 3) * 32;
    const int wc0  = (wid >> 2) * 32;

    float accl[2][4][4], accr[2][4][4];
#pragma unroll
    for (int mt = 0; mt < 2; mt++)
#pragma unroll
        for (int nt = 0; nt < 4; nt++)
#pragma unroll
            for (int i = 0; i < 4; i++) { accl[mt][nt][i] = 0.f; accr[mt][nt][i] = 0.f; }

#pragma unroll
    for (int ks = 0; ks < 16; ks++) {
        const int k0 = ks * 8;
        float a[2][4], bl[4][2], br[4][2];
#pragma unroll
        for (int mt = 0; mt < 2; mt++) {
            int r = wr0 + mt * 16 + gid;
            a[mt][0] = As[r * 132 + k0 + tig];
            a[mt][1] = As[(r + 8) * 132 + k0 + tig];
            a[mt][2] = As[r * 132 + k0 + tig + 4];
            a[mt][3] = As[(r + 8) * 132 + k0 + tig + 4];
        }
#pragma unroll
        for (int nt = 0; nt < 4; nt++) {
            int c = wc0 + nt * 8 + gid;
            bl[nt][0] = Wsl[(k0 + tig) * 76 + c];
            bl[nt][1] = Wsl[(k0 + tig + 4) * 76 + c];
            br[nt][0] = Wsr[(k0 + tig) * 76 + c];
            br[nt][1] = Wsr[(k0 + tig + 4) * 76 + c];
        }
#pragma unroll
        for (int mt = 0; mt < 2; mt++)
#pragma unroll
            for (int nt = 0; nt < 4; nt++) {
                mma_tf32(accl[mt][nt], a[mt], bl[nt]);
                mma_tf32(accr[mt][nt], a[mt], br[nt]);
            }
    }

#pragma unroll
    for (int mt = 0; mt < 2; mt++) {
        int r = row0 + wr0 + mt * 16 + gid;
#pragma unroll
        for (int nt = 0; nt < 4; nt++) {
            int c = cw + wc0 + nt * 8 + 2 * tig;
            if (r < N_NODES) {
                *(__half2*)&Y[(size_t)r * M_OUT + c] =
                    __floats2half2_rn(accl[mt][nt][0], accl[mt][nt][1]);
                *(float2*)&R[(size_t)r * M_OUT + c] =
                    make_float2(accr[mt][nt][0], accr[mt][nt][1]);
            }
            if (r + 8 < N_NODES) {
                *(__half2*)&Y[(size_t)(r + 8) * M_OUT + c] =
                    __floats2half2_rn(accl[mt][nt][2], accl[mt][nt][3]);
                *(float2*)&R[(size_t)(r + 8) * M_OUT + c] =
                    make_float2(accr[mt][nt][2], accr[mt][nt][3]);
            }
        }
    }
}

// ---------------- gather-mean aggregation (fp16 y, fp32 accum) ----------------
template <int COLS, bool RELU>
__global__ __launch_bounds__(256) void k_agg(const __half* __restrict__ y,
                                             const float* __restrict__ r,
                                             const float* __restrict__ bias,
                                             float* __restrict__ out) {
    int gw   = (blockIdx.x * blockDim.x + threadIdx.x) >> 5;
    int lane = threadIdx.x & 31;
    if (gw >= N_NODES) return;

    int p0 = g_ptr[gw];
    int p1 = g_ptr[gw + 1];
    float inv = 1.0f / (float)max(p1 - p0, 1);

    if (COLS == 128) {
        const int c = lane * 4;                  // 4 halfs per lane (8B)
        float4 a0 = make_float4(0.f, 0.f, 0.f, 0.f);
        float4 a1 = make_float4(0.f, 0.f, 0.f, 0.f);
        int j = p0;
        for (; j + 4 <= p1; j += 4) {
            int s0 = __ldg(&g_srcs[j]),     s1 = __ldg(&g_srcs[j + 1]);
            int s2 = __ldg(&g_srcs[j + 2]), s3 = __ldg(&g_srcs[j + 3]);
            __half2 v0a = __ldg((const __half2*)&y[(size_t)s0 * 128 + c]);
            __half2 v0b = __ldg((const __half2*)&y[(size_t)s0 * 128 + c + 2]);
            __half2 v1a = __ldg((const __half2*)&y[(size_t)s1 * 128 + c]);
            __half2 v1b = __ldg((const __half2*)&y[(size_t)s1 * 128 + c + 2]);
            __half2 v2a = __ldg((const __half2*)&y[(size_t)s2 * 128 + c]);
            __half2 v2b = __ldg((const __half2*)&y[(size_t)s2 * 128 + c + 2]);
            __half2 v3a = __ldg((const __half2*)&y[(size_t)s3 * 128 + c]);
            __half2 v3b = __ldg((const __half2*)&y[(size_t)s3 * 128 + c + 2]);
            float2 f;
            f = __half22float2(v0a); a0.x += f.x; a0.y += f.y;
            f = __half22float2(v0b); a0.z += f.x; a0.w += f.y;
            f = __half22float2(v1a); a1.x += f.x; a1.y += f.y;
            f = __half22float2(v1b); a1.z += f.x; a1.w += f.y;
            f = __half22float2(v2a); a0.x += f.x; a0.y += f.y;
            f = __half22float2(v2b); a0.z += f.x; a0.w += f.y;
            f = __half22float2(v3a); a1.x += f.x; a1.y += f.y;
            f = __half22float2(v3b); a1.z += f.x; a1.w += f.y;
        }
        for (; j < p1; j++) {
            int s = __ldg(&g_srcs[j]);
            __half2 va = __ldg((const __half2*)&y[(size_t)s * 128 + c]);
            __half2 vb = __ldg((const __half2*)&y[(size_t)s * 128 + c + 2]);
            float2 f;
            f = __half22float2(va); a0.x += f.x; a0.y += f.y;
            f = __half22float2(vb); a0.z += f.x; a0.w += f.y;
        }
        float4 rb = *(const float4*)&r[(size_t)gw * 128 + c];
        float4 bb = __ldg((const float4*)&bias[c]);
        float4 o;
        o.x = fmaf(a0.x + a1.x, inv, bb.x + rb.x);
        o.y = fmaf(a0.y + a1.y, inv, bb.y + rb.y);
        o.z = fmaf(a0.z + a1.z, inv, bb.z + rb.z);
        o.w = fmaf(a0.w + a1.w, inv, bb.w + rb.w);
        if (RELU) {
            o.x = fmaxf(o.x, 0.f); o.y = fmaxf(o.y, 0.f);
            o.z = fmaxf(o.z, 0.f); o.w = fmaxf(o.w, 0.f);
        }
        *(float4*)&out[(size_t)gw * 128 + c] = o;
    } else {
        const int c = lane * 2;                  // 2 halfs per lane (4B)
        float2 a0 = make_float2(0.f, 0.f);
        float2 a1 = make_float2(0.f, 0.f);
        int j = p0;
        for (; j + 4 <= p1; j += 4) {
            int s0 = __ldg(&g_srcs[j]),     s1 = __ldg(&g_srcs[j + 1]);
            int s2 = __ldg(&g_srcs[j + 2]), s3 = __ldg(&g_srcs[j + 3]);
            float2 f0 = __half22float2(__ldg((const __half2*)&y[(size_t)s0 * 64 + c]));
            float2 f1 = __half22float2(__ldg((const __half2*)&y[(size_t)s1 * 64 + c]));
            float2 f2 = __half22float2(__ldg((const __half2*)&y[(size_t)s2 * 64 + c]));
            float2 f3 = __half22float2(__ldg((const __half2*)&y[(size_t)s3 * 64 + c]));
            a0.x += f0.x; a0.y += f0.y;
            a1.x += f1.x; a1.y += f1.y;
            a0.x += f2.x; a0.y += f2.y;
            a1.x += f3.x; a1.y += f3.y;
        }
        for (; j < p1; j++) {
            int s = __ldg(&g_srcs[j]);
            float2 f = __half22float2(__ldg((const __half2*)&y[(size_t)s * 64 + c]));
            a0.x += f.x; a0.y += f.y;
        }
        float2 rb = *(const float2*)&r[(size_t)gw * 64 + c];
        float2 bb = __ldg((const float2*)&bias[c]);
        float2 o;
        o.x = fmaf(a0.x + a1.x, inv, bb.x + rb.x);
        o.y = fmaf(a0.y + a1.y, inv, bb.y + rb.y);
        if (RELU) { o.x = fmaxf(o.x, 0.f); o.y = fmaxf(o.y, 0.f); }
        *(float2*)&out[(size_t)gw * 64 + c] = o;
    }
}

// ---------------- launch ----------------
extern "C" void kernel_launch(void* const* d_in, const int* in_sizes, int n_in,
                              void* d_out, int out_size) {
    const float* x   = (const float*)d_in[0];
    const float* Wl1 = (const float*)d_in[1];
    const float* bl1 = (const float*)d_in[2];
    const float* Wr1 = (const float*)d_in[3];
    const float* Wl2 = (const float*)d_in[4];
    const float* bl2 = (const float*)d_in[5];
    const float* Wr2 = (const float*)d_in[6];
    const int*   ei  = (const int*)d_in[7];
    const int* src = ei;
    const int* dst = ei + N_EDGES;
    float* out = (float*)d_out;

    __half* yhp;
    float *r1p, *hp;
    cudaGetSymbolAddress((void**)&yhp, g_yh);
    cudaGetSymbolAddress((void**)&r1p, g_r1);
    cudaGetSymbolAddress((void**)&hp,  g_h);

    constexpr int SMEM = (128 * 132 + 2 * 128 * 76) * 4;   // 145408 B
    cudaFuncSetAttribute(k_mma<128>,
                         cudaFuncAttributeMaxDynamicSharedMemorySize, SMEM);
    cudaFuncSetAttribute(k_mma<64>,
                         cudaFuncAttributeMaxDynamicSharedMemorySize, SMEM);

    // CSR build
    k_zero   <<<(N_NODES + 255) / 256, 256>>>();
    k_hist   <<<(N_EDGES + 255) / 256, 256>>>(dst);
    k_scan_a <<<SCAN_BLOCKS, 1024>>>();
    k_scan_c <<<SCAN_BLOCKS, 1024>>>();
    k_scatter<<<(N_EDGES + 255) / 256, 256>>>(src, dst);

    const int n_tiles = (N_NODES + 127) / 128;   // 391

    // layer 1
    k_mma<128><<<dim3(n_tiles, 2), 256, SMEM>>>(x, Wl1, Wr1, yhp, r1p);
    k_agg<128, true><<<(N_NODES + 7) / 8, 256>>>(yhp, r1p, bl1, hp);

    // layer 2
    k_mma<64><<<dim3(n_tiles, 1), 256, SMEM>>>(hp, Wl2, Wr2, yhp, r1p);
    k_agg<64, false><<<(N_NODES + 7) / 8, 256>>>(yhp, r1p, bl2, out);
}

// round 6
// speedup vs baseline: 1.8880x; 1.2605x over previous
#include <cuda_runtime.h>
#include <cuda_fp16.h>
#include <cstdint>

#define N_NODES 50000
#define N_EDGES 800000
#define H1      128
#define H2      64
#define SCAT_B  ((N_EDGES + 255) / 256)

// ---------------- scratch (no allocations allowed) ----------------
__device__ int    g_deg[N_NODES];
__device__ int    g_ptr[N_NODES + 1];
__device__ int    g_rank[N_EDGES];
__device__ int    g_srcs[N_EDGES];
__device__ int    g_bsum[64];
__device__ __half g_yh[N_NODES * H1];   // fp16 lin_l output (reused by layer 2)
__device__ float  g_r1[N_NODES * H1];   // fp32 lin_r output (reused by layer 2)
__device__ __half g_hh[N_NODES * H1];   // fp16 hidden h

// ---------------- fp16 mma helper ----------------
__device__ __forceinline__ void mma_f16(float* c, const uint32_t* a, const uint32_t* b) {
    asm volatile(
        "mma.sync.aligned.m16n8k16.row.col.f32.f16.f16.f32 "
        "{%0,%1,%2,%3}, {%4,%5,%6,%7}, {%8,%9}, {%0,%1,%2,%3};"
        : "+f"(c[0]), "+f"(c[1]), "+f"(c[2]), "+f"(c[3])
        : "r"(a[0]), "r"(a[1]), "r"(a[2]), "r"(a[3]),
          "r"(b[0]), "r"(b[1]));
}

// ---------------- CSR build ----------------
__global__ void k_hist(const int* __restrict__ dst) {
    int e = blockIdx.x * blockDim.x + threadIdx.x;
    if (e < N_EDGES) g_rank[e] = atomicAdd(&g_deg[dst[e]], 1);
}
#define SCAN_BLOCKS 49
__global__ __launch_bounds__(1024) void k_scan_a() {
    __shared__ int s[1024];
    int t = threadIdx.x;
    int i = blockIdx.x * 1024 + t;
    int val = (i < N_NODES) ? g_deg[i] : 0;
    s[t] = val;
    __syncthreads();
#pragma unroll
    for (int off = 1; off < 1024; off <<= 1) {
        int v = (t >= off) ? s[t - off] : 0;
        __syncthreads();
        s[t] += v;
        __syncthreads();
    }
    if (i < N_NODES) g_ptr[i] = s[t] - val;          // exclusive within block
    if (t == 1023) g_bsum[blockIdx.x] = s[t];        // block total
}
__global__ __launch_bounds__(1024) void k_scan_c() {
    __shared__ int off_s;
    int t = threadIdx.x;
    if (t == 0) {
        int acc = 0;
        for (int b = 0; b < blockIdx.x; b++) acc += g_bsum[b];
        off_s = acc;
    }
    __syncthreads();
    int i = blockIdx.x * 1024 + t;
    if (i < N_NODES) g_ptr[i] += off_s;
    if (i == 0) g_ptr[N_NODES] = N_EDGES;
}

// ---------------- GEMM body (fp16 mma.sync m16n8k16) ----------------
// A tile: 128 rows x 128 K. Col block cw: 64 cols of Wl (-> fp16 Y) and Wr (-> fp32 R).
template <int M_OUT, typename TA>
__device__ __forceinline__ void gemm_body(__half* smh,
                                          int row0, int cw,
                                          const TA* __restrict__ A,
                                          const float* __restrict__ Wl,
                                          const float* __restrict__ Wr,
                                          __half* __restrict__ Y,
                                          float* __restrict__ R) {
    __half* As  = smh;                     // [128][136]
    __half* Wsl = smh + 128 * 136;         // [64][136]  (transposed: n rows, k cols)
    __half* Wsr = Wsl + 64 * 136;          // [64][136]

    const int tid = threadIdx.x;

    // --- stage A ---
    if (sizeof(TA) == 4) {   // fp32 input: convert
        const float* Af = (const float*)A;
        for (int idx = tid; idx < 128 * 32; idx += 256) {
            int r = idx >> 5, q = (idx & 31) << 2;
            float4 v = make_float4(0.f, 0.f, 0.f, 0.f);
            int gr = row0 + r;
            if (gr < N_NODES) v = *(const float4*)&Af[(size_t)gr * 128 + q];
            __half2 h0 = __floats2half2_rn(v.x, v.y);
            __half2 h1 = __floats2half2_rn(v.z, v.w);
            *(uint2*)&As[r * 136 + q] =
                make_uint2(*(uint32_t*)&h0, *(uint32_t*)&h1);
        }
    } else {                 // fp16 input: straight copy
        const __half* Ah = (const __half*)A;
        for (int idx = tid; idx < 128 * 16; idx += 256) {
            int r = idx >> 4, q = (idx & 15) << 3;
            uint4 v = make_uint4(0, 0, 0, 0);
            int gr = row0 + r;
            if (gr < N_NODES) v = *(const uint4*)&Ah[(size_t)gr * 128 + q];
            *(uint4*)&As[r * 136 + q] = v;
        }
    }
    // --- stage W transposed: Ws[n][k] ---
    for (int idx = tid; idx < 128 * 16; idx += 256) {
        int k = idx >> 4, q = (idx & 15) << 2;
        float4 vl = *(const float4*)&Wl[(size_t)k * M_OUT + cw + q];
        float4 vr = *(const float4*)&Wr[(size_t)k * M_OUT + cw + q];
        Wsl[(q + 0) * 136 + k] = __float2half_rn(vl.x);
        Wsl[(q + 1) * 136 + k] = __float2half_rn(vl.y);
        Wsl[(q + 2) * 136 + k] = __float2half_rn(vl.z);
        Wsl[(q + 3) * 136 + k] = __float2half_rn(vl.w);
        Wsr[(q + 0) * 136 + k] = __float2half_rn(vr.x);
        Wsr[(q + 1) * 136 + k] = __float2half_rn(vr.y);
        Wsr[(q + 2) * 136 + k] = __float2half_rn(vr.z);
        Wsr[(q + 3) * 136 + k] = __float2half_rn(vr.w);
    }
    __syncthreads();

    const int wid  = tid >> 5;
    const int lane = tid & 31;
    const int gid  = lane >> 2;
    const int tig  = lane & 3;
    const int wr0  = (wid & 3) * 32;
    const int wc0  = (wid >> 2) * 32;

    float accl[2][4][4], accr[2][4][4];
#pragma unroll
    for (int mt = 0; mt < 2; mt++)
#pragma unroll
        for (int nt = 0; nt < 4; nt++)
#pragma unroll
            for (int i = 0; i < 4; i++) { accl[mt][nt][i] = 0.f; accr[mt][nt][i] = 0.f; }

#pragma unroll
    for (int ks = 0; ks < 8; ks++) {
        const int k0 = ks * 16;
        uint32_t a[2][4], bl[4][2], br[4][2];
#pragma unroll
        for (int mt = 0; mt < 2; mt++) {
            int base = (wr0 + mt * 16 + gid) * 136 + k0 + 2 * tig;
            a[mt][0] = *(const uint32_t*)&As[base];
            a[mt][1] = *(const uint32_t*)&As[base + 8 * 136];
            a[mt][2] = *(const uint32_t*)&As[base + 8];
            a[mt][3] = *(const uint32_t*)&As[base + 8 * 136 + 8];
        }
#pragma unroll
        for (int nt = 0; nt < 4; nt++) {
            int bb = (wc0 + nt * 8 + gid) * 136 + k0 + 2 * tig;
            bl[nt][0] = *(const uint32_t*)&Wsl[bb];
            bl[nt][1] = *(const uint32_t*)&Wsl[bb + 8];
            br[nt][0] = *(const uint32_t*)&Wsr[bb];
            br[nt][1] = *(const uint32_t*)&Wsr[bb + 8];
        }
#pragma unroll
        for (int mt = 0; mt < 2; mt++)
#pragma unroll
            for (int nt = 0; nt < 4; nt++) {
                mma_f16(accl[mt][nt], a[mt], bl[nt]);
                mma_f16(accr[mt][nt], a[mt], br[nt]);
            }
    }

    // --- store ---
#pragma unroll
    for (int mt = 0; mt < 2; mt++) {
        int r = row0 + wr0 + mt * 16 + gid;
#pragma unroll
        for (int nt = 0; nt < 4; nt++) {
            int c = cw + wc0 + nt * 8 + 2 * tig;
            if (r < N_NODES) {
                __half2 h = __floats2half2_rn(accl[mt][nt][0], accl[mt][nt][1]);
                *(__half2*)&Y[(size_t)r * M_OUT + c] = h;
                *(float2*)&R[(size_t)r * M_OUT + c] =
                    make_float2(accr[mt][nt][0], accr[mt][nt][1]);
            }
            if (r + 8 < N_NODES) {
                __half2 h = __floats2half2_rn(accl[mt][nt][2], accl[mt][nt][3]);
                *(__half2*)&Y[(size_t)(r + 8) * M_OUT + c] = h;
                *(float2*)&R[(size_t)(r + 8) * M_OUT + c] =
                    make_float2(accr[mt][nt][2], accr[mt][nt][3]);
            }
        }
    }
}

// ---------------- fat kernel: scatter blocks + layer-1 GEMM blocks ----------------
__global__ __launch_bounds__(256) void k_fat1(const int* __restrict__ src,
                                              const int* __restrict__ dst,
                                              const float* __restrict__ A,
                                              const float* __restrict__ Wl,
                                              const float* __restrict__ Wr,
                                              __half* __restrict__ Y,
                                              float* __restrict__ R) {
    extern __shared__ __half smh[];
    if (blockIdx.x < SCAT_B) {
        int e = blockIdx.x * 256 + threadIdx.x;
        if (e < N_EDGES)
            g_srcs[g_ptr[dst[e]] + g_rank[e]] = src[e];
        return;
    }
    int b = blockIdx.x - SCAT_B;
    gemm_body<H1, float>(smh, (b >> 1) * 128, (b & 1) * 64, A, Wl, Wr, Y, R);
}

// ---------------- layer-2 GEMM (fp16 input) ----------------
__global__ __launch_bounds__(256) void k_mma2(const __half* __restrict__ A,
                                              const float* __restrict__ Wl,
                                              const float* __restrict__ Wr,
                                              __half* __restrict__ Y,
                                              float* __restrict__ R) {
    extern __shared__ __half smh[];
    gemm_body<H2, __half>(smh, blockIdx.x * 128, 0, A, Wl, Wr, Y, R);
}

// ---------------- gather-mean aggregation (fp16 y, fp32 accum) ----------------
// OUT_T: __half (layer 1 hidden) or float (final output)
template <int COLS, bool RELU, typename OUT_T>
__global__ __launch_bounds__(256) void k_agg(const __half* __restrict__ y,
                                             const float* __restrict__ r,
                                             const float* __restrict__ bias,
                                             OUT_T* __restrict__ out) {
    int gw   = (blockIdx.x * blockDim.x + threadIdx.x) >> 5;
    int lane = threadIdx.x & 31;
    if (gw >= N_NODES) return;

    int p0 = g_ptr[gw];
    int p1 = g_ptr[gw + 1];
    float inv = 1.0f / (float)max(p1 - p0, 1);

    if (COLS == 128) {
        const int c = lane * 4;                  // 4 halfs per lane
        float4 a0 = make_float4(0.f, 0.f, 0.f, 0.f);
        float4 a1 = make_float4(0.f, 0.f, 0.f, 0.f);
        int j = p0;
        for (; j + 4 <= p1; j += 4) {
            int s0 = __ldg(&g_srcs[j]),     s1 = __ldg(&g_srcs[j + 1]);
            int s2 = __ldg(&g_srcs[j + 2]), s3 = __ldg(&g_srcs[j + 3]);
            uint2 u0 = __ldg((const uint2*)&y[(size_t)s0 * 128 + c]);
            uint2 u1 = __ldg((const uint2*)&y[(size_t)s1 * 128 + c]);
            uint2 u2 = __ldg((const uint2*)&y[(size_t)s2 * 128 + c]);
            uint2 u3 = __ldg((const uint2*)&y[(size_t)s3 * 128 + c]);
            float2 f;
            f = __half22float2(*(__half2*)&u0.x); a0.x += f.x; a0.y += f.y;
            f = __half22float2(*(__half2*)&u0.y); a0.z += f.x; a0.w += f.y;
            f = __half22float2(*(__half2*)&u1.x); a1.x += f.x; a1.y += f.y;
            f = __half22float2(*(__half2*)&u1.y); a1.z += f.x; a1.w += f.y;
            f = __half22float2(*(__half2*)&u2.x); a0.x += f.x; a0.y += f.y;
            f = __half22float2(*(__half2*)&u2.y); a0.z += f.x; a0.w += f.y;
            f = __half22float2(*(__half2*)&u3.x); a1.x += f.x; a1.y += f.y;
            f = __half22float2(*(__half2*)&u3.y); a1.z += f.x; a1.w += f.y;
        }
        for (; j < p1; j++) {
            int s = __ldg(&g_srcs[j]);
            uint2 u = __ldg((const uint2*)&y[(size_t)s * 128 + c]);
            float2 f;
            f = __half22float2(*(__half2*)&u.x); a0.x += f.x; a0.y += f.y;
            f = __half22float2(*(__half2*)&u.y); a0.z += f.x; a0.w += f.y;
        }
        float4 rb = *(const float4*)&r[(size_t)gw * 128 + c];
        float4 bb = __ldg((const float4*)&bias[c]);
        float4 o;
        o.x = fmaf(a0.x + a1.x, inv, bb.x + rb.x);
        o.y = fmaf(a0.y + a1.y, inv, bb.y + rb.y);
        o.z = fmaf(a0.z + a1.z, inv, bb.z + rb.z);
        o.w = fmaf(a0.w + a1.w, inv, bb.w + rb.w);
        if (RELU) {
            o.x = fmaxf(o.x, 0.f); o.y = fmaxf(o.y, 0.f);
            o.z = fmaxf(o.z, 0.f); o.w = fmaxf(o.w, 0.f);
        }
        if (sizeof(OUT_T) == 2) {
            __half2 h0 = __floats2half2_rn(o.x, o.y);
            __half2 h1 = __floats2half2_rn(o.z, o.w);
            *(uint2*)&((__half*)out)[(size_t)gw * 128 + c] =
                make_uint2(*(uint32_t*)&h0, *(uint32_t*)&h1);
        } else {
            *(float4*)&((float*)out)[(size_t)gw * 128 + c] = o;
        }
    } else {
        const int c = lane * 2;
        float2 a0 = make_float2(0.f, 0.f);
        float2 a1 = make_float2(0.f, 0.f);
        int j = p0;
        for (; j + 4 <= p1; j += 4) {
            int s0 = __ldg(&g_srcs[j]),     s1 = __ldg(&g_srcs[j + 1]);
            int s2 = __ldg(&g_srcs[j + 2]), s3 = __ldg(&g_srcs[j + 3]);
            float2 f0 = __half22float2(__ldg((const __half2*)&y[(size_t)s0 * 64 + c]));
            float2 f1 = __half22float2(__ldg((const __half2*)&y[(size_t)s1 * 64 + c]));
            float2 f2 = __half22float2(__ldg((const __half2*)&y[(size_t)s2 * 64 + c]));
            float2 f3 = __half22float2(__ldg((const __half2*)&y[(size_t)s3 * 64 + c]));
            a0.x += f0.x; a0.y += f0.y;
            a1.x += f1.x; a1.y += f1.y;
            a0.x += f2.x; a0.y += f2.y;
            a1.x += f3.x; a1.y += f3.y;
        }
        for (; j < p1; j++) {
            int s = __ldg(&g_srcs[j]);
            float2 f = __half22float2(__ldg((const __half2*)&y[(size_t)s * 64 + c]));
            a0.x += f.x; a0.y += f.y;
        }
        float2 rb = *(const float2*)&r[(size_t)gw * 64 + c];
        float2 bb = __ldg((const float2*)&bias[c]);
        float2 o;
        o.x = fmaf(a0.x + a1.x, inv, bb.x + rb.x);
        o.y = fmaf(a0.y + a1.y, inv, bb.y + rb.y);
        if (RELU) { o.x = fmaxf(o.x, 0.f); o.y = fmaxf(o.y, 0.f); }
        if (sizeof(OUT_T) == 2) {
            *(__half2*)&((__half*)out)[(size_t)gw * 64 + c] =
                __floats2half2_rn(o.x, o.y);
        } else {
            *(float2*)&((float*)out)[(size_t)gw * 64 + c] = o;
        }
    }
}

// ---------------- launch ----------------
extern "C" void kernel_launch(void* const* d_in, const int* in_sizes, int n_in,
                              void* d_out, int out_size) {
    const float* x   = (const float*)d_in[0];
    const float* Wl1 = (const float*)d_in[1];
    const float* bl1 = (const float*)d_in[2];
    const float* Wr1 = (const float*)d_in[3];
    const float* Wl2 = (const float*)d_in[4];
    const float* bl2 = (const float*)d_in[5];
    const float* Wr2 = (const float*)d_in[6];
    const int*   ei  = (const int*)d_in[7];
    const int* src = ei;
    const int* dst = ei + N_EDGES;
    float* out = (float*)d_out;

    __half *yhp, *hhp;
    float* r1p;
    int* degp;
    cudaGetSymbolAddress((void**)&yhp, g_yh);
    cudaGetSymbolAddress((void**)&hhp, g_hh);
    cudaGetSymbolAddress((void**)&r1p, g_r1);
    cudaGetSymbolAddress((void**)&degp, g_deg);

    constexpr int SMEM = (128 * 136 + 2 * 64 * 136) * 2;   // 69632 B
    cudaFuncSetAttribute(k_fat1,
                         cudaFuncAttributeMaxDynamicSharedMemorySize, SMEM);
    cudaFuncSetAttribute(k_mma2,
                         cudaFuncAttributeMaxDynamicSharedMemorySize, SMEM);

    const int n_tiles = (N_NODES + 127) / 128;   // 391

    // CSR build
    cudaMemsetAsync(degp, 0, N_NODES * sizeof(int));
    k_hist  <<<(N_EDGES + 255) / 256, 256>>>(dst);
    k_scan_a<<<SCAN_BLOCKS, 1024>>>();
    k_scan_c<<<SCAN_BLOCKS, 1024>>>();

    // scatter + layer-1 GEMM fused launch
    k_fat1<<<SCAT_B + n_tiles * 2, 256, SMEM>>>(src, dst, x, Wl1, Wr1, yhp, r1p);
    k_agg<128, true, __half><<<(N_NODES + 7) / 8, 256>>>(yhp, r1p, bl1, hhp);

    // layer 2
    k_mma2<<<n_tiles, 256, SMEM>>>(hhp, Wl2, Wr2, yhp, r1p);
    k_agg<64, false, float><<<(N_NODES + 7) / 8, 256>>>(yhp, r1p, bl2, out);
}

// round 7
// speedup vs baseline: 2.0915x; 1.1078x over previous
#include <cuda_runtime.h>
#include <cuda_fp16.h>
#include <cstdint>

#define N_NODES 50000
#define N_EDGES 800000
#define H1      128
#define H2      64
#define SCAT_B  ((N_EDGES + 511) / 512)

// ---------------- scratch (no allocations allowed) ----------------
__device__ int    g_deg[N_NODES];
__device__ int    g_ptr[N_NODES + 1];
__device__ int    g_rank[N_EDGES];
__device__ int    g_srcs[N_EDGES];
__device__ int    g_bsum[64];
__device__ __half g_yh[N_NODES * H1];   // fp16 lin_l output (reused by layer 2)
__device__ float  g_r1[N_NODES * H1];   // fp32 lin_r output (reused by layer 2)
__device__ __half g_hh[N_NODES * H1];   // fp16 hidden h

// ---------------- fp16 mma helper ----------------
__device__ __forceinline__ void mma_f16(float* c, const uint32_t* a, const uint32_t* b) {
    asm volatile(
        "mma.sync.aligned.m16n8k16.row.col.f32.f16.f16.f32 "
        "{%0,%1,%2,%3}, {%4,%5,%6,%7}, {%8,%9}, {%0,%1,%2,%3};"
        : "+f"(c[0]), "+f"(c[1]), "+f"(c[2]), "+f"(c[3])
        : "r"(a[0]), "r"(a[1]), "r"(a[2]), "r"(a[3]),
          "r"(b[0]), "r"(b[1]));
}

// ---------------- CSR build ----------------
__global__ void k_hist(const int* __restrict__ dst) {
    int e = blockIdx.x * blockDim.x + threadIdx.x;
    if (e < N_EDGES) g_rank[e] = atomicAdd(&g_deg[dst[e]], 1);
}
#define SCAN_BLOCKS 49
__global__ __launch_bounds__(1024) void k_scan_a() {
    __shared__ int s[1024];
    int t = threadIdx.x;
    int i = blockIdx.x * 1024 + t;
    int val = (i < N_NODES) ? g_deg[i] : 0;
    s[t] = val;
    __syncthreads();
#pragma unroll
    for (int off = 1; off < 1024; off <<= 1) {
        int v = (t >= off) ? s[t - off] : 0;
        __syncthreads();
        s[t] += v;
        __syncthreads();
    }
    if (i < N_NODES) g_ptr[i] = s[t] - val;          // exclusive within block
    if (t == 1023) g_bsum[blockIdx.x] = s[t];        // block total
}
__global__ __launch_bounds__(1024) void k_scan_c() {
    __shared__ int off_s;
    int t = threadIdx.x;
    if (t == 0) {
        int acc = 0;
        for (int b = 0; b < blockIdx.x; b++) acc += g_bsum[b];
        off_s = acc;
    }
    __syncthreads();
    int i = blockIdx.x * 1024 + t;
    if (i < N_NODES) g_ptr[i] += off_s;
    if (i == 0) g_ptr[N_NODES] = N_EDGES;
}

// ---------------- GEMM body (fp16 mma.sync m16n8k16, 512 threads) ----------------
// A tile: 128 rows x 128 K. One 64-col block cw of Wl (-> fp16 Y) and Wr (-> fp32 R).
// 16 warps in 4x4 grid over 128 rows x 128 virtual cols ([Wl-block | Wr-block]).
template <int M_OUT, typename TA>
__device__ __forceinline__ void gemm_body(__half* smh,
                                          int row0, int cw,
                                          const TA* __restrict__ A,
                                          const float* __restrict__ Wl,
                                          const float* __restrict__ Wr,
                                          __half* __restrict__ Y,
                                          float* __restrict__ R) {
    __half* As  = smh;                     // [128][136]
    __half* Wsl = smh + 128 * 136;         // [64][136]  transposed: [n][k]
    __half* Wsr = Wsl + 64 * 136;          // [64][136]

    const int tid = threadIdx.x;

    // --- stage A ---
    if (sizeof(TA) == 4) {   // fp32 input: convert
        const float* Af = (const float*)A;
        for (int idx = tid; idx < 128 * 32; idx += 512) {
            int r = idx >> 5, q = (idx & 31) << 2;
            float4 v = make_float4(0.f, 0.f, 0.f, 0.f);
            int gr = row0 + r;
            if (gr < N_NODES) v = *(const float4*)&Af[(size_t)gr * 128 + q];
            __half2 h0 = __floats2half2_rn(v.x, v.y);
            __half2 h1 = __floats2half2_rn(v.z, v.w);
            *(uint2*)&As[r * 136 + q] =
                make_uint2(*(uint32_t*)&h0, *(uint32_t*)&h1);
        }
    } else {                 // fp16 input: straight copy
        const __half* Ah = (const __half*)A;
        for (int idx = tid; idx < 128 * 16; idx += 512) {
            int r = idx >> 4, q = (idx & 15) << 3;
            uint4 v = make_uint4(0, 0, 0, 0);
            int gr = row0 + r;
            if (gr < N_NODES) v = *(const uint4*)&Ah[(size_t)gr * 128 + q];
            *(uint4*)&As[r * 136 + q] = v;
        }
    }
    // --- stage W transposed: Ws[n][k] ---
    for (int idx = tid; idx < 128 * 16; idx += 512) {
        int k = idx >> 4, q = (idx & 15) << 2;
        float4 vl = *(const float4*)&Wl[(size_t)k * M_OUT + cw + q];
        float4 vr = *(const float4*)&Wr[(size_t)k * M_OUT + cw + q];
        Wsl[(q + 0) * 136 + k] = __float2half_rn(vl.x);
        Wsl[(q + 1) * 136 + k] = __float2half_rn(vl.y);
        Wsl[(q + 2) * 136 + k] = __float2half_rn(vl.z);
        Wsl[(q + 3) * 136 + k] = __float2half_rn(vl.w);
        Wsr[(q + 0) * 136 + k] = __float2half_rn(vr.x);
        Wsr[(q + 1) * 136 + k] = __float2half_rn(vr.y);
        Wsr[(q + 2) * 136 + k] = __float2half_rn(vr.z);
        Wsr[(q + 3) * 136 + k] = __float2half_rn(vr.w);
    }
    __syncthreads();

    const int wid  = tid >> 5;
    const int lane = tid & 31;
    const int gid  = lane >> 2;
    const int tig  = lane & 3;
    const int wr0  = (wid & 3) * 32;          // warp rows
    const int wc0  = (wid >> 2) * 32;         // warp cols in [0,128): 0-63 Wl, 64-127 Wr
    const bool isR = (wc0 >= 64);
    const int  wcl = wc0 & 63;                // col within the 64-wide W block
    const __half* Ws = isR ? Wsr : Wsl;

    float acc[2][4][4];
#pragma unroll
    for (int mt = 0; mt < 2; mt++)
#pragma unroll
        for (int nt = 0; nt < 4; nt++)
#pragma unroll
            for (int i = 0; i < 4; i++) acc[mt][nt][i] = 0.f;

#pragma unroll
    for (int ks = 0; ks < 8; ks++) {
        const int k0 = ks * 16;
        uint32_t a[2][4], b[4][2];
#pragma unroll
        for (int mt = 0; mt < 2; mt++) {
            int base = (wr0 + mt * 16 + gid) * 136 + k0 + 2 * tig;
            a[mt][0] = *(const uint32_t*)&As[base];
            a[mt][1] = *(const uint32_t*)&As[base + 8 * 136];
            a[mt][2] = *(const uint32_t*)&As[base + 8];
            a[mt][3] = *(const uint32_t*)&As[base + 8 * 136 + 8];
        }
#pragma unroll
        for (int nt = 0; nt < 4; nt++) {
            int bb = (wcl + nt * 8 + gid) * 136 + k0 + 2 * tig;
            b[nt][0] = *(const uint32_t*)&Ws[bb];
            b[nt][1] = *(const uint32_t*)&Ws[bb + 8];
        }
#pragma unroll
        for (int mt = 0; mt < 2; mt++)
#pragma unroll
            for (int nt = 0; nt < 4; nt++)
                mma_f16(acc[mt][nt], a[mt], b[nt]);
    }

    // --- store ---
#pragma unroll
    for (int mt = 0; mt < 2; mt++) {
        int r = row0 + wr0 + mt * 16 + gid;
#pragma unroll
        for (int nt = 0; nt < 4; nt++) {
            int c = cw + wcl + nt * 8 + 2 * tig;
            if (isR) {
                if (r < N_NODES)
                    *(float2*)&R[(size_t)r * M_OUT + c] =
                        make_float2(acc[mt][nt][0], acc[mt][nt][1]);
                if (r + 8 < N_NODES)
                    *(float2*)&R[(size_t)(r + 8) * M_OUT + c] =
                        make_float2(acc[mt][nt][2], acc[mt][nt][3]);
            } else {
                if (r < N_NODES)
                    *(__half2*)&Y[(size_t)r * M_OUT + c] =
                        __floats2half2_rn(acc[mt][nt][0], acc[mt][nt][1]);
                if (r + 8 < N_NODES)
                    *(__half2*)&Y[(size_t)(r + 8) * M_OUT + c] =
                        __floats2half2_rn(acc[mt][nt][2], acc[mt][nt][3]);
            }
        }
    }
}

// ---------------- fat kernel: scatter blocks + layer-1 GEMM blocks ----------------
__global__ __launch_bounds__(512, 2) void k_fat1(const int* __restrict__ src,
                                                 const int* __restrict__ dst,
                                                 const float* __restrict__ A,
                                                 const float* __restrict__ Wl,
                                                 const float* __restrict__ Wr,
                                                 __half* __restrict__ Y,
                                                 float* __restrict__ R) {
    extern __shared__ __half smh[];
    if (blockIdx.x < SCAT_B) {
        int e = blockIdx.x * 512 + threadIdx.x;
        if (e < N_EDGES)
            g_srcs[g_ptr[dst[e]] + g_rank[e]] = src[e];
        return;
    }
    int b = blockIdx.x - SCAT_B;
    gemm_body<H1, float>(smh, (b >> 1) * 128, (b & 1) * 64, A, Wl, Wr, Y, R);
}

// ---------------- layer-2 GEMM (fp16 input) ----------------
__global__ __launch_bounds__(512, 2) void k_mma2(const __half* __restrict__ A,
                                                 const float* __restrict__ Wl,
                                                 const float* __restrict__ Wr,
                                                 __half* __restrict__ Y,
                                                 float* __restrict__ R) {
    extern __shared__ __half smh[];
    gemm_body<H2, __half>(smh, blockIdx.x * 128, 0, A, Wl, Wr, Y, R);
}

// ---------------- gather-mean aggregation (fp16 y, fp32 accum) ----------------
template <int COLS, bool RELU, typename OUT_T>
__global__ __launch_bounds__(256) void k_agg(const __half* __restrict__ y,
                                             const float* __restrict__ r,
                                             const float* __restrict__ bias,
                                             OUT_T* __restrict__ out) {
    int gw   = (blockIdx.x * blockDim.x + threadIdx.x) >> 5;
    int lane = threadIdx.x & 31;
    if (gw >= N_NODES) return;

    int p0 = g_ptr[gw];
    int p1 = g_ptr[gw + 1];
    float inv = 1.0f / (float)max(p1 - p0, 1);

    if (COLS == 128) {
        const int c = lane * 4;
        float4 a0 = make_float4(0.f, 0.f, 0.f, 0.f);
        float4 a1 = make_float4(0.f, 0.f, 0.f, 0.f);
        int j = p0;
        for (; j + 4 <= p1; j += 4) {
            int s0 = __ldg(&g_srcs[j]),     s1 = __ldg(&g_srcs[j + 1]);
            int s2 = __ldg(&g_srcs[j + 2]), s3 = __ldg(&g_srcs[j + 3]);
            uint2 u0 = __ldg((const uint2*)&y[(size_t)s0 * 128 + c]);
            uint2 u1 = __ldg((const uint2*)&y[(size_t)s1 * 128 + c]);
            uint2 u2 = __ldg((const uint2*)&y[(size_t)s2 * 128 + c]);
            uint2 u3 = __ldg((const uint2*)&y[(size_t)s3 * 128 + c]);
            float2 f;
            f = __half22float2(*(__half2*)&u0.x); a0.x += f.x; a0.y += f.y;
            f = __half22float2(*(__half2*)&u0.y); a0.z += f.x; a0.w += f.y;
            f = __half22float2(*(__half2*)&u1.x); a1.x += f.x; a1.y += f.y;
            f = __half22float2(*(__half2*)&u1.y); a1.z += f.x; a1.w += f.y;
            f = __half22float2(*(__half2*)&u2.x); a0.x += f.x; a0.y += f.y;
            f = __half22float2(*(__half2*)&u2.y); a0.z += f.x; a0.w += f.y;
            f = __half22float2(*(__half2*)&u3.x); a1.x += f.x; a1.y += f.y;
            f = __half22float2(*(__half2*)&u3.y); a1.z += f.x; a1.w += f.y;
        }
        for (; j < p1; j++) {
            int s = __ldg(&g_srcs[j]);
            uint2 u = __ldg((const uint2*)&y[(size_t)s * 128 + c]);
            float2 f;
            f = __half22float2(*(__half2*)&u.x); a0.x += f.x; a0.y += f.y;
            f = __half22float2(*(__half2*)&u.y); a0.z += f.x; a0.w += f.y;
        }
        float4 rb = *(const float4*)&r[(size_t)gw * 128 + c];
        float4 bb = __ldg((const float4*)&bias[c]);
        float4 o;
        o.x = fmaf(a0.x + a1.x, inv, bb.x + rb.x);
        o.y = fmaf(a0.y + a1.y, inv, bb.y + rb.y);
        o.z = fmaf(a0.z + a1.z, inv, bb.z + rb.z);
        o.w = fmaf(a0.w + a1.w, inv, bb.w + rb.w);
        if (RELU) {
            o.x = fmaxf(o.x, 0.f); o.y = fmaxf(o.y, 0.f);
            o.z = fmaxf(o.z, 0.f); o.w = fmaxf(o.w, 0.f);
        }
        if (sizeof(OUT_T) == 2) {
            __half2 h0 = __floats2half2_rn(o.x, o.y);
            __half2 h1 = __floats2half2_rn(o.z, o.w);
            *(uint2*)&((__half*)out)[(size_t)gw * 128 + c] =
                make_uint2(*(uint32_t*)&h0, *(uint32_t*)&h1);
        } else {
            *(float4*)&((float*)out)[(size_t)gw * 128 + c] = o;
        }
    } else {
        const int c = lane * 2;
        float2 a0 = make_float2(0.f, 0.f);
        float2 a1 = make_float2(0.f, 0.f);
        int j = p0;
        for (; j + 4 <= p1; j += 4) {
            int s0 = __ldg(&g_srcs[j]),     s1 = __ldg(&g_srcs[j + 1]);
            int s2 = __ldg(&g_srcs[j + 2]), s3 = __ldg(&g_srcs[j + 3]);
            float2 f0 = __half22float2(__ldg((const __half2*)&y[(size_t)s0 * 64 + c]));
            float2 f1 = __half22float2(__ldg((const __half2*)&y[(size_t)s1 * 64 + c]));
            float2 f2 = __half22float2(__ldg((const __half2*)&y[(size_t)s2 * 64 + c]));
            float2 f3 = __half22float2(__ldg((const __half2*)&y[(size_t)s3 * 64 + c]));
            a0.x += f0.x; a0.y += f0.y;
            a1.x += f1.x; a1.y += f1.y;
            a0.x += f2.x; a0.y += f2.y;
            a1.x += f3.x; a1.y += f3.y;
        }
        for (; j < p1; j++) {
            int s = __ldg(&g_srcs[j]);
            float2 f = __half22float2(__ldg((const __half2*)&y[(size_t)s * 64 + c]));
            a0.x += f.x; a0.y += f.y;
        }
        float2 rb = *(const float2*)&r[(size_t)gw * 64 + c];
        float2 bb = __ldg((const float2*)&bias[c]);
        float2 o;
        o.x = fmaf(a0.x + a1.x, inv, bb.x + rb.x);
        o.y = fmaf(a0.y + a1.y, inv, bb.y + rb.y);
        if (RELU) { o.x = fmaxf(o.x, 0.f); o.y = fmaxf(o.y, 0.f); }
        if (sizeof(OUT_T) == 2) {
            *(__half2*)&((__half*)out)[(size_t)gw * 64 + c] =
                __floats2half2_rn(o.x, o.y);
        } else {
            *(float2*)&((float*)out)[(size_t)gw * 64 + c] = o;
        }
    }
}

// ---------------- launch ----------------
extern "C" void kernel_launch(void* const* d_in, const int* in_sizes, int n_in,
                              void* d_out, int out_size) {
    const float* x   = (const float*)d_in[0];
    const float* Wl1 = (const float*)d_in[1];
    const float* bl1 = (const float*)d_in[2];
    const float* Wr1 = (const float*)d_in[3];
    const float* Wl2 = (const float*)d_in[4];
    const float* bl2 = (const float*)d_in[5];
    const float* Wr2 = (const float*)d_in[6];
    const int*   ei  = (const int*)d_in[7];
    const int* src = ei;
    const int* dst = ei + N_EDGES;
    float* out = (float*)d_out;

    __half *yhp, *hhp;
    float* r1p;
    int* degp;
    cudaGetSymbolAddress((void**)&yhp, g_yh);
    cudaGetSymbolAddress((void**)&hhp, g_hh);
    cudaGetSymbolAddress((void**)&r1p, g_r1);
    cudaGetSymbolAddress((void**)&degp, g_deg);

    constexpr int SMEM = (128 * 136 + 2 * 64 * 136) * 2;   // 69632 B
    cudaFuncSetAttribute(k_fat1,
                         cudaFuncAttributeMaxDynamicSharedMemorySize, SMEM);
    cudaFuncSetAttribute(k_mma2,
                         cudaFuncAttributeMaxDynamicSharedMemorySize, SMEM);

    const int n_tiles = (N_NODES + 127) / 128;   // 391

    // CSR build
    cudaMemsetAsync(degp, 0, N_NODES * sizeof(int));
    k_hist  <<<(N_EDGES + 255) / 256, 256>>>(dst);
    k_scan_a<<<SCAN_BLOCKS, 1024>>>();
    k_scan_c<<<SCAN_BLOCKS, 1024>>>();

    // scatter + layer-1 GEMM fused launch
    k_fat1<<<SCAT_B + n_tiles * 2, 512, SMEM>>>(src, dst, x, Wl1, Wr1, yhp, r1p);
    k_agg<128, true, __half><<<(N_NODES + 7) / 8, 256>>>(yhp, r1p, bl1, hhp);

    // layer 2
    k_mma2<<<n_tiles, 512, SMEM>>>(hhp, Wl2, Wr2, yhp, r1p);
    k_agg<64, false, float><<<(N_NODES + 7) / 8, 256>>>(yhp, r1p, bl2, out);
}

// round 8
// speedup vs baseline: 2.5054x; 1.1979x over previous
#include <cuda_runtime.h>
#include <cuda_fp16.h>
#include <cstdint>

#define N_NODES 50000
#define N_EDGES 800000
#define H1      128
#define H2      64
#define HB      1563                       // hist blocks (800000/512)
#define XB      1563                       // x-convert blocks (6.4M/4096)
#define WB      96                         // W-transpose blocks (49152/512)
#define SCAT_B  1563                       // scatter blocks

// ---------------- scratch (no allocations allowed) ----------------
__device__ int    g_deg[N_NODES];
__device__ int    g_ptr[N_NODES + 1];
__device__ int    g_rank[N_EDGES];
__device__ int    g_srcs[N_EDGES];
__device__ int    g_bsum[64];
__device__ __half g_xh[N_NODES * 128];     // fp16 x
__device__ __half g_Wt1[256 * 128];        // [Wl1^T ; Wr1^T]  fp16, [n][k]
__device__ __half g_Wt2[128 * 128];        // [Wl2^T ; Wr2^T]  fp16, [n][k]
__device__ __half g_yh[N_NODES * H1];      // fp16 lin_l output (reused layer 2)
__device__ float  g_r1[N_NODES * H1];      // fp32 lin_r output (reused layer 2)
__device__ __half g_hh[N_NODES * H1];      // fp16 hidden h

// ---------------- PTX helpers ----------------
__device__ __forceinline__ void mma_f16(float* c, const uint32_t* a, const uint32_t* b) {
    asm volatile(
        "mma.sync.aligned.m16n8k16.row.col.f32.f16.f16.f32 "
        "{%0,%1,%2,%3}, {%4,%5,%6,%7}, {%8,%9}, {%0,%1,%2,%3};"
        : "+f"(c[0]), "+f"(c[1]), "+f"(c[2]), "+f"(c[3])
        : "r"(a[0]), "r"(a[1]), "r"(a[2]), "r"(a[3]),
          "r"(b[0]), "r"(b[1]));
}
#define LDSM_X4(r, addr) \
    asm volatile("ldmatrix.sync.aligned.m8n8.x4.shared.b16 {%0,%1,%2,%3}, [%4];" \
        : "=r"((r)[0]), "=r"((r)[1]), "=r"((r)[2]), "=r"((r)[3]) : "r"(addr))
__device__ __forceinline__ void cp16(uint32_t s, const void* g) {
    asm volatile("cp.async.cg.shared.global [%0], [%1], 16;" :: "r"(s), "l"(g));
}
__device__ __forceinline__ void cp_commit_wait() {
    asm volatile("cp.async.commit_group;");
    asm volatile("cp.async.wait_group 0;" ::: "memory");
}

// ---------------- fat prep: hist + x->fp16 + W transpose ----------------
__global__ __launch_bounds__(512) void k_fath(const int* __restrict__ dst,
                                              const float* __restrict__ x,
                                              const float* __restrict__ Wl1,
                                              const float* __restrict__ Wr1,
                                              const float* __restrict__ Wl2,
                                              const float* __restrict__ Wr2) {
    int b = blockIdx.x, t = threadIdx.x;
    if (b < HB) {
        int e = b * 512 + t;
        if (e < N_EDGES) g_rank[e] = atomicAdd(&g_deg[dst[e]], 1);
    } else if (b < HB + XB) {
        int chunk = (b - HB) * 512 + t;
        if (chunk < N_NODES * 16) {          // 8 floats per chunk
            int i8 = chunk * 8;
            float4 v0 = *(const float4*)&x[i8];
            float4 v1 = *(const float4*)&x[i8 + 4];
            __half2 h0 = __floats2half2_rn(v0.x, v0.y);
            __half2 h1 = __floats2half2_rn(v0.z, v0.w);
            __half2 h2 = __floats2half2_rn(v1.x, v1.y);
            __half2 h3 = __floats2half2_rn(v1.z, v1.w);
            *(uint4*)&g_xh[i8] = make_uint4(*(uint32_t*)&h0, *(uint32_t*)&h1,
                                            *(uint32_t*)&h2, *(uint32_t*)&h3);
        }
    } else {
        int i = (b - HB - XB) * 512 + t;
        if (i < 256 * 128) {
            int n = i >> 7, k = i & 127;
            float w = (n < 128) ? Wl1[k * 128 + n] : Wr1[k * 128 + (n - 128)];
            g_Wt1[i] = __float2half_rn(w);
        } else {
            int j = i - 256 * 128;
            if (j < 128 * 128) {
                int n = j >> 7, k = j & 127;
                float w = (n < 64) ? Wl2[k * 64 + n] : Wr2[k * 64 + (n - 64)];
                g_Wt2[j] = __float2half_rn(w);
            }
        }
    }
}

// ---------------- scan ----------------
#define SCAN_BLOCKS 49
__global__ __launch_bounds__(1024) void k_scan_a() {
    __shared__ int s[1024];
    int t = threadIdx.x;
    int i = blockIdx.x * 1024 + t;
    int val = (i < N_NODES) ? g_deg[i] : 0;
    s[t] = val;
    __syncthreads();
#pragma unroll
    for (int off = 1; off < 1024; off <<= 1) {
        int v = (t >= off) ? s[t - off] : 0;
        __syncthreads();
        s[t] += v;
        __syncthreads();
    }
    if (i < N_NODES) g_ptr[i] = s[t] - val;
    if (t == 1023) g_bsum[blockIdx.x] = s[t];
}
__global__ __launch_bounds__(1024) void k_scan_c() {
    __shared__ int off_s;
    int t = threadIdx.x;
    if (t == 0) {
        int acc = 0;
        for (int b = 0; b < blockIdx.x; b++) acc += g_bsum[b];
        off_s = acc;
    }
    __syncthreads();
    int i = blockIdx.x * 1024 + t;
    if (i < N_NODES) g_ptr[i] += off_s;
    if (i == 0) g_ptr[N_NODES] = N_EDGES;
}

// ---------------- GEMM body: cp.async staging + ldmatrix + fp16 mma ----------------
// A: fp16 [*,128]; Wt: fp16 [2*M_OUT rows n][128 k]. Output 128 cols = [Y(64) | R(64)] block.
// smem: A [128][136], W [128][136] halfs (272B rows).
template <int M_OUT>
__device__ __forceinline__ void gemm_body(__half* smh,
                                          int row0, int cw,
                                          const __half* __restrict__ A,
                                          const __half* __restrict__ Wt,
                                          __half* __restrict__ Y,
                                          float* __restrict__ R) {
    const int tid = threadIdx.x;
    uint32_t sbase = (uint32_t)__cvta_generic_to_shared(smh);
    const uint32_t sA = sbase;
    const uint32_t sW = sbase + 128 * 272;

    // --- stage A: 128 rows x 16 chunks of 16B ---
    for (int i = tid; i < 2048; i += 512) {
        int r = i >> 4, c = i & 15;
        int gr = row0 + r;
        uint32_t d = sA + r * 272 + c * 16;
        if (gr < N_NODES) cp16(d, &A[(size_t)gr * 128 + c * 8]);
        else *(uint4*)(smh + (r * 136 + c * 8)) = make_uint4(0, 0, 0, 0);
    }
    // --- stage W: 128 n-rows x 16 chunks; rows 0-63 -> Y cols, 64-127 -> R cols ---
    for (int i = tid; i < 2048; i += 512) {
        int j = i >> 4, c = i & 15;
        int srcrow = cw + ((j < 64) ? j : j + M_OUT - 64);
        cp16(sW + j * 272 + c * 16, &Wt[(size_t)srcrow * 128 + c * 8]);
    }
    cp_commit_wait();
    __syncthreads();

    const int wid  = tid >> 5;
    const int lane = tid & 31;
    const int wr0  = (wid & 3) * 32;          // warp rows
    const int wc0  = (wid >> 2) * 32;         // warp cols in [0,128)
    const int lrow = lane & 7;

    // ldmatrix lane addresses
    const uint32_t aBase = sA + (uint32_t)((wr0 + lrow + ((lane >> 3) & 1) * 8) * 272
                                           + ((lane >> 4) * 8) * 2);
    const uint32_t bBase = sW + (uint32_t)((wc0 + lrow + ((lane >> 4) & 1) * 8) * 272
                                           + (((lane >> 3) & 1) * 8) * 2);

    float acc[2][4][4];
#pragma unroll
    for (int mt = 0; mt < 2; mt++)
#pragma unroll
        for (int nt = 0; nt < 4; nt++)
#pragma unroll
            for (int i = 0; i < 4; i++) acc[mt][nt][i] = 0.f;

#pragma unroll
    for (int ks = 0; ks < 8; ks++) {
        uint32_t a0[4], a1[4], b0[4], b1[4];
        LDSM_X4(a0, aBase + ks * 32);
        LDSM_X4(a1, aBase + 16 * 272 + ks * 32);
        LDSM_X4(b0, bBase + ks * 32);             // n rows wc0..wc0+15 -> nt 0,1
        LDSM_X4(b1, bBase + 16 * 272 + ks * 32);  // n rows +16        -> nt 2,3
        mma_f16(acc[0][0], a0, &b0[0]);
        mma_f16(acc[0][1], a0, &b0[2]);
        mma_f16(acc[0][2], a0, &b1[0]);
        mma_f16(acc[0][3], a0, &b1[2]);
        mma_f16(acc[1][0], a1, &b0[0]);
        mma_f16(acc[1][1], a1, &b0[2]);
        mma_f16(acc[1][2], a1, &b1[0]);
        mma_f16(acc[1][3], a1, &b1[2]);
    }

    // --- store ---
    const int gid = lane >> 2;
    const int tig = lane & 3;
    const bool isR = (wc0 >= 64);
    const int  wcl = wc0 & 63;
#pragma unroll
    for (int mt = 0; mt < 2; mt++) {
        int r = row0 + wr0 + mt * 16 + gid;
#pragma unroll
        for (int nt = 0; nt < 4; nt++) {
            int c = cw + wcl + nt * 8 + 2 * tig;
            if (isR) {
                if (r < N_NODES)
                    *(float2*)&R[(size_t)r * M_OUT + c] =
                        make_float2(acc[mt][nt][0], acc[mt][nt][1]);
                if (r + 8 < N_NODES)
                    *(float2*)&R[(size_t)(r + 8) * M_OUT + c] =
                        make_float2(acc[mt][nt][2], acc[mt][nt][3]);
            } else {
                if (r < N_NODES)
                    *(__half2*)&Y[(size_t)r * M_OUT + c] =
                        __floats2half2_rn(acc[mt][nt][0], acc[mt][nt][1]);
                if (r + 8 < N_NODES)
                    *(__half2*)&Y[(size_t)(r + 8) * M_OUT + c] =
                        __floats2half2_rn(acc[mt][nt][2], acc[mt][nt][3]);
            }
        }
    }
}

// ---------------- fat kernel: scatter blocks + layer-1 GEMM blocks ----------------
__global__ __launch_bounds__(512, 2) void k_fat1(const int* __restrict__ src,
                                                 const int* __restrict__ dst,
                                                 __half* __restrict__ Y,
                                                 float* __restrict__ R) {
    extern __shared__ __half smh[];
    if (blockIdx.x < SCAT_B) {
        int e = blockIdx.x * 512 + threadIdx.x;
        if (e < N_EDGES)
            g_srcs[g_ptr[dst[e]] + g_rank[e]] = src[e];
        return;
    }
    int b = blockIdx.x - SCAT_B;
    gemm_body<H1>(smh, (b >> 1) * 128, (b & 1) * 64, g_xh, g_Wt1, Y, R);
}

// ---------------- layer-2 GEMM ----------------
__global__ __launch_bounds__(512, 2) void k_mma2(__half* __restrict__ Y,
                                                 float* __restrict__ R) {
    extern __shared__ __half smh[];
    gemm_body<H2>(smh, blockIdx.x * 128, 0, g_hh, g_Wt2, Y, R);
}

// ---------------- gather-mean aggregation (fp16 y, fp32 accum) ----------------
template <int COLS, bool RELU, typename OUT_T>
__global__ __launch_bounds__(256) void k_agg(const __half* __restrict__ y,
                                             const float* __restrict__ r,
                                             const float* __restrict__ bias,
                                             OUT_T* __restrict__ out) {
    int gw   = (blockIdx.x * blockDim.x + threadIdx.x) >> 5;
    int lane = threadIdx.x & 31;
    if (gw >= N_NODES) return;

    int p0 = g_ptr[gw];
    int p1 = g_ptr[gw + 1];
    float inv = 1.0f / (float)max(p1 - p0, 1);

    if (COLS == 128) {
        const int c = lane * 4;
        float4 a0 = make_float4(0.f, 0.f, 0.f, 0.f);
        float4 a1 = make_float4(0.f, 0.f, 0.f, 0.f);
        int j = p0;
        for (; j + 4 <= p1; j += 4) {
            int s0 = __ldg(&g_srcs[j]),     s1 = __ldg(&g_srcs[j + 1]);
            int s2 = __ldg(&g_srcs[j + 2]), s3 = __ldg(&g_srcs[j + 3]);
            uint2 u0 = __ldg((const uint2*)&y[(size_t)s0 * 128 + c]);
            uint2 u1 = __ldg((const uint2*)&y[(size_t)s1 * 128 + c]);
            uint2 u2 = __ldg((const uint2*)&y[(size_t)s2 * 128 + c]);
            uint2 u3 = __ldg((const uint2*)&y[(size_t)s3 * 128 + c]);
            float2 f;
            f = __half22float2(*(__half2*)&u0.x); a0.x += f.x; a0.y += f.y;
            f = __half22float2(*(__half2*)&u0.y); a0.z += f.x; a0.w += f.y;
            f = __half22float2(*(__half2*)&u1.x); a1.x += f.x; a1.y += f.y;
            f = __half22float2(*(__half2*)&u1.y); a1.z += f.x; a1.w += f.y;
            f = __half22float2(*(__half2*)&u2.x); a0.x += f.x; a0.y += f.y;
            f = __half22float2(*(__half2*)&u2.y); a0.z += f.x; a0.w += f.y;
            f = __half22float2(*(__half2*)&u3.x); a1.x += f.x; a1.y += f.y;
            f = __half22float2(*(__half2*)&u3.y); a1.z += f.x; a1.w += f.y;
        }
        for (; j < p1; j++) {
            int s = __ldg(&g_srcs[j]);
            uint2 u = __ldg((const uint2*)&y[(size_t)s * 128 + c]);
            float2 f;
            f = __half22float2(*(__half2*)&u.x); a0.x += f.x; a0.y += f.y;
            f = __half22float2(*(__half2*)&u.y); a0.z += f.x; a0.w += f.y;
        }
        float4 rb = *(const float4*)&r[(size_t)gw * 128 + c];
        float4 bb = __ldg((const float4*)&bias[c]);
        float4 o;
        o.x = fmaf(a0.x + a1.x, inv, bb.x + rb.x);
        o.y = fmaf(a0.y + a1.y, inv, bb.y + rb.y);
        o.z = fmaf(a0.z + a1.z, inv, bb.z + rb.z);
        o.w = fmaf(a0.w + a1.w, inv, bb.w + rb.w);
        if (RELU) {
            o.x = fmaxf(o.x, 0.f); o.y = fmaxf(o.y, 0.f);
            o.z = fmaxf(o.z, 0.f); o.w = fmaxf(o.w, 0.f);
        }
        if (sizeof(OUT_T) == 2) {
            __half2 h0 = __floats2half2_rn(o.x, o.y);
            __half2 h1 = __floats2half2_rn(o.z, o.w);
            *(uint2*)&((__half*)out)[(size_t)gw * 128 + c] =
                make_uint2(*(uint32_t*)&h0, *(uint32_t*)&h1);
        } else {
            *(float4*)&((float*)out)[(size_t)gw * 128 + c] = o;
        }
    } else {
        const int c = lane * 2;
        float2 a0 = make_float2(0.f, 0.f);
        float2 a1 = make_float2(0.f, 0.f);
        int j = p0;
        for (; j + 4 <= p1; j += 4) {
            int s0 = __ldg(&g_srcs[j]),     s1 = __ldg(&g_srcs[j + 1]);
            int s2 = __ldg(&g_srcs[j + 2]), s3 = __ldg(&g_srcs[j + 3]);
            float2 f0 = __half22float2(__ldg((const __half2*)&y[(size_t)s0 * 64 + c]));
            float2 f1 = __half22float2(__ldg((const __half2*)&y[(size_t)s1 * 64 + c]));
            float2 f2 = __half22float2(__ldg((const __half2*)&y[(size_t)s2 * 64 + c]));
            float2 f3 = __half22float2(__ldg((const __half2*)&y[(size_t)s3 * 64 + c]));
            a0.x += f0.x; a0.y += f0.y;
            a1.x += f1.x; a1.y += f1.y;
            a0.x += f2.x; a0.y += f2.y;
            a1.x += f3.x; a1.y += f3.y;
        }
        for (; j < p1; j++) {
            int s = __ldg(&g_srcs[j]);
            float2 f = __half22float2(__ldg((const __half2*)&y[(size_t)s * 64 + c]));
            a0.x += f.x; a0.y += f.y;
        }
        float2 rb = *(const float2*)&r[(size_t)gw * 64 + c];
        float2 bb = __ldg((const float2*)&bias[c]);
        float2 o;
        o.x = fmaf(a0.x + a1.x, inv, bb.x + rb.x);
        o.y = fmaf(a0.y + a1.y, inv, bb.y + rb.y);
        if (RELU) { o.x = fmaxf(o.x, 0.f); o.y = fmaxf(o.y, 0.f); }
        if (sizeof(OUT_T) == 2) {
            *(__half2*)&((__half*)out)[(size_t)gw * 64 + c] =
                __floats2half2_rn(o.x, o.y);
        } else {
            *(float2*)&((float*)out)[(size_t)gw * 64 + c] = o;
        }
    }
}

// ---------------- launch ----------------
extern "C" void kernel_launch(void* const* d_in, const int* in_sizes, int n_in,
                              void* d_out, int out_size) {
    const float* x   = (const float*)d_in[0];
    const float* Wl1 = (const float*)d_in[1];
    const float* bl1 = (const float*)d_in[2];
    const float* Wr1 = (const float*)d_in[3];
    const float* Wl2 = (const float*)d_in[4];
    const float* bl2 = (const float*)d_in[5];
    const float* Wr2 = (const float*)d_in[6];
    const int*   ei  = (const int*)d_in[7];
    const int* src = ei;
    const int* dst = ei + N_EDGES;
    float* out = (float*)d_out;

    __half *yhp, *hhp;
    float* r1p;
    int* degp;
    cudaGetSymbolAddress((void**)&yhp, g_yh);
    cudaGetSymbolAddress((void**)&hhp, g_hh);
    cudaGetSymbolAddress((void**)&r1p, g_r1);
    cudaGetSymbolAddress((void**)&degp, g_deg);

    constexpr int SMEM = 2 * 128 * 272;   // 69632 B
    cudaFuncSetAttribute(k_fat1,
                         cudaFuncAttributeMaxDynamicSharedMemorySize, SMEM);
    cudaFuncSetAttribute(k_mma2,
                         cudaFuncAttributeMaxDynamicSharedMemorySize, SMEM);

    const int n_tiles = (N_NODES + 127) / 128;   // 391

    // prep: zero deg, then hist + x->fp16 + W transpose in one fat launch
    cudaMemsetAsync(degp, 0, N_NODES * sizeof(int));
    k_fath  <<<HB + XB + WB, 512>>>(dst, x, Wl1, Wr1, Wl2, Wr2);
    k_scan_a<<<SCAN_BLOCKS, 1024>>>();
    k_scan_c<<<SCAN_BLOCKS, 1024>>>();

    // scatter + layer-1 GEMM fused launch
    k_fat1<<<SCAT_B + n_tiles * 2, 512, SMEM>>>(src, dst, yhp, r1p);
    k_agg<128, true, __half><<<(N_NODES + 7) / 8, 256>>>(yhp, r1p, bl1, hhp);

    // layer 2
    k_mma2<<<n_tiles, 512, SMEM>>>(yhp, r1p);
    k_agg<64, false, float><<<(N_NODES + 7) / 8, 256>>>(yhp, r1p, bl2, out);
}